// round 4
// baseline (speedup 1.0000x reference)
#include <cuda_runtime.h>
#include <cuda_bf16.h>
#include <math.h>
#include <stdint.h>

// Problem constants
#define Bq   8
#define Lq   1024
#define Eq   512
#define Hq   8
#define FFq  2048
#define Mq   (Bq*Lq)          // 8192 tokens

typedef __nv_bfloat16 bf16;

// ---------------- scratch (static device globals; allocation-free) ----------
__device__ float g_x [Mq*Eq];        // current activations (fp32, residual path)
__device__ float g_sv[Bq*Hq*Lq];     // per-(b,h,i) 0.125/sum(exp)
__device__ float g_A [Bq*Lq*Lq];     // head-avg attn (fp32, softmax2 input)
__device__ float g_t [Mq*Eq];        // sa / ff temp (fp32)
__device__ float g_P [(size_t)Bq*Hq*Lq*Lq];  // per-head exp(logits), causal tiles

// split (hi/lo bf16) buffers
__device__ bf16 g_xh [Mq*Eq],     g_xl [Mq*Eq];
__device__ bf16 g_qkh[Mq*1024],   g_qkl[Mq*1024];
__device__ bf16 g_awh[(size_t)Bq*Lq*Lq], g_awl[(size_t)Bq*Lq*Lq];
__device__ bf16 g_xth[Bq*Eq*Lq],  g_xtl[Bq*Eq*Lq];
__device__ bf16 g_hh [Mq*FFq],    g_hl [Mq*FFq];
__device__ bf16 g_Wqh[4*1024*512], g_Wql[4*1024*512];
__device__ bf16 g_W1h[4*2048*512], g_W1l[4*2048*512];
__device__ bf16 g_W2h[4*512*2048], g_W2l[4*512*2048];

// ---------------- helpers ----------------------------------------------------
__device__ __forceinline__ float warp_sum(float s){
    #pragma unroll
    for (int o=16;o;o>>=1) s += __shfl_xor_sync(0xffffffffu, s, o);
    return s;
}

__device__ __forceinline__ void bsplit(float x0, float x1, uint32_t& hi, uint32_t& lo){
    bf16 h0 = __float2bfloat16_rn(x0);
    bf16 h1 = __float2bfloat16_rn(x1);
    bf16 l0 = __float2bfloat16_rn(x0 - __bfloat162float(h0));
    bf16 l1 = __float2bfloat16_rn(x1 - __bfloat162float(h1));
    hi = (uint32_t)__bfloat16_as_ushort(h0) | ((uint32_t)__bfloat16_as_ushort(h1) << 16);
    lo = (uint32_t)__bfloat16_as_ushort(l0) | ((uint32_t)__bfloat16_as_ushort(l1) << 16);
}

__device__ __forceinline__ void mma16816(float* c, const uint32_t* a, const uint32_t* b){
    asm volatile(
        "mma.sync.aligned.m16n8k16.row.col.f32.bf16.bf16.f32 "
        "{%0,%1,%2,%3}, {%4,%5,%6,%7}, {%8,%9}, {%0,%1,%2,%3};\n"
        : "+f"(c[0]), "+f"(c[1]), "+f"(c[2]), "+f"(c[3])
        : "r"(a[0]), "r"(a[1]), "r"(a[2]), "r"(a[3]), "r"(b[0]), "r"(b[1]));
}

// ============================================================================
// Split kernels: fp32 -> bf16 hi/lo (optionally keep fp32 copy)
// ============================================================================
__global__ __launch_bounds__(256) void split_arr(
    const float* __restrict__ in, bf16* __restrict__ oh, bf16* __restrict__ ol, int n4)
{
    int i = blockIdx.x*256 + threadIdx.x;
    if (i >= n4) return;
    float4 v = ((const float4*)in)[i];
    uint32_t h0,l0,h1,l1;
    bsplit(v.x, v.y, h0, l0);
    bsplit(v.z, v.w, h1, l1);
    ((uint2*)oh)[i] = make_uint2(h0, h1);
    ((uint2*)ol)[i] = make_uint2(l0, l1);
}

__global__ __launch_bounds__(256) void split_copy(
    const float* __restrict__ in, float* __restrict__ out,
    bf16* __restrict__ oh, bf16* __restrict__ ol, int n4)
{
    int i = blockIdx.x*256 + threadIdx.x;
    if (i >= n4) return;
    float4 v = ((const float4*)in)[i];
    ((float4*)out)[i] = v;
    uint32_t h0,l0,h1,l1;
    bsplit(v.x, v.y, h0, l0);
    bsplit(v.z, v.w, h1, l1);
    ((uint2*)oh)[i] = make_uint2(h0, h1);
    ((uint2*)ol)[i] = make_uint2(l0, l1);
}

// ============================================================================
// Tensor-core GEMM NT on pre-split bf16 inputs (3-product fp32-equivalent):
//   C[M,N] = A[M,K] * B[N,K]^T (+bias, relu), batched via z.
// Outputs: fp32 C and/or split bf16 (Ch, Cl).
// Block tile 128x128, BK=32, 256 threads. Hot loop: LDS + HMMA only.
// ============================================================================
template<int RELU, int WF32, int WSPLIT>
__global__ __launch_bounds__(256, 2) void mma_gemm2(
    const bf16* __restrict__ Ah, const bf16* __restrict__ Al,
    const bf16* __restrict__ Bh, const bf16* __restrict__ Bl,
    const float* __restrict__ bias,
    float* __restrict__ C, bf16* __restrict__ Ch, bf16* __restrict__ Cl,
    int M, int N, int K, long sA, long sB, long sC, int causal)
{
    __shared__ uint32_t sAh[128*20], sAl[128*20], sBh[128*20], sBl[128*20];
    const int bm = blockIdx.y * 128, bn = blockIdx.x * 128;
    const bf16* Abh = Ah + (size_t)blockIdx.z * sA;
    const bf16* Abl = Al + (size_t)blockIdx.z * sA;
    const bf16* Bbh = Bh + (size_t)blockIdx.z * sB;
    const bf16* Bbl = Bl + (size_t)blockIdx.z * sB;

    const int t    = threadIdx.x;
    const int lane = t & 31, wid = t >> 5;
    const int wm   = wid >> 2, wn = wid & 3;
    const int gid  = lane >> 2, tig = lane & 3;

    float acc[4][4][4];
    #pragma unroll
    for (int i=0;i<4;i++)
        #pragma unroll
        for (int j=0;j<4;j++)
            #pragma unroll
            for (int q=0;q<4;q++) acc[i][j][q] = 0.f;

    const int fr = t >> 1, half = t & 1;
    const uint4* A4h = (const uint4*)(Abh + (size_t)(bm+fr)*K);
    const uint4* A4l = (const uint4*)(Abl + (size_t)(bm+fr)*K);
    const uint4* B4h = (const uint4*)(Bbh + (size_t)(bn+fr)*K);
    const uint4* B4l = (const uint4*)(Bbl + (size_t)(bn+fr)*K);
    uint4* dAh = (uint4*)(sAh + fr*20 + half*8);
    uint4* dAl = (uint4*)(sAl + fr*20 + half*8);
    uint4* dBh = (uint4*)(sBh + fr*20 + half*8);
    uint4* dBl = (uint4*)(sBl + fr*20 + half*8);

    const int kend = causal ? (bm + 128) : K;
    for (int k0 = 0; k0 < kend; k0 += 32){
        const int gi = (k0 >> 3) + half*2;          // uint4 index (8 bf16 each)
        uint4 vah0 = A4h[gi], vah1 = A4h[gi+1];
        uint4 val0 = A4l[gi], val1 = A4l[gi+1];
        uint4 vbh0 = B4h[gi], vbh1 = B4h[gi+1];
        uint4 vbl0 = B4l[gi], vbl1 = B4l[gi+1];
        __syncthreads();
        dAh[0] = vah0; dAh[1] = vah1;
        dAl[0] = val0; dAl[1] = val1;
        dBh[0] = vbh0; dBh[1] = vbh1;
        dBl[0] = vbl0; dBl[1] = vbl1;
        __syncthreads();

        #pragma unroll
        for (int ks=0; ks<2; ks++){
            const int ci = tig + ks*8;
            uint32_t bhf[4][2], blf[4][2];
            #pragma unroll
            for (int ni=0;ni<4;ni++){
                int n = (wn*32 + ni*8 + gid)*20;
                bhf[ni][0] = sBh[n + ci];  bhf[ni][1] = sBh[n + ci + 4];
                blf[ni][0] = sBl[n + ci];  blf[ni][1] = sBl[n + ci + 4];
            }
            #pragma unroll
            for (int mi=0;mi<4;mi++){
                int m0 = (wm*64 + mi*16 + gid)*20;
                uint32_t ah[4] = {sAh[m0+ci], sAh[m0+160+ci], sAh[m0+ci+4], sAh[m0+160+ci+4]};
                uint32_t al[4] = {sAl[m0+ci], sAl[m0+160+ci], sAl[m0+ci+4], sAl[m0+160+ci+4]};
                #pragma unroll
                for (int ni=0;ni<4;ni++){
                    mma16816(acc[mi][ni], ah, bhf[ni]);
                    mma16816(acc[mi][ni], ah, blf[ni]);
                    mma16816(acc[mi][ni], al, bhf[ni]);
                }
            }
        }
    }

    float* Cb  = WF32 ? C + (size_t)blockIdx.z * sC : nullptr;
    #pragma unroll
    for (int mi=0;mi<4;mi++){
        int row = bm + wm*64 + mi*16 + gid;
        #pragma unroll
        for (int ni=0;ni<4;ni++){
            int col = bn + wn*32 + ni*8 + tig*2;
            float2 v0 = make_float2(acc[mi][ni][0], acc[mi][ni][1]);
            float2 v1 = make_float2(acc[mi][ni][2], acc[mi][ni][3]);
            if (bias){
                float2 bb = *(const float2*)(bias + col);
                v0.x += bb.x; v0.y += bb.y; v1.x += bb.x; v1.y += bb.y;
            }
            if (RELU){
                v0.x=fmaxf(v0.x,0.f); v0.y=fmaxf(v0.y,0.f);
                v1.x=fmaxf(v1.x,0.f); v1.y=fmaxf(v1.y,0.f);
            }
            if (WF32){
                *(float2*)(Cb + (size_t)row    *N + col) = v0;
                *(float2*)(Cb + (size_t)(row+8)*N + col) = v1;
            }
            if (WSPLIT){
                uint32_t h0,l0,h1,l1;
                bsplit(v0.x, v0.y, h0, l0);
                bsplit(v1.x, v1.y, h1, l1);
                *(uint32_t*)(Ch + (size_t)row    *N + col) = h0;
                *(uint32_t*)(Cl + (size_t)row    *N + col) = l0;
                *(uint32_t*)(Ch + (size_t)(row+8)*N + col) = h1;
                *(uint32_t*)(Cl + (size_t)(row+8)*N + col) = l1;
            }
        }
    }
}

// ============================================================================
// Fused attention exp kernel on pre-split qk:
// per (b,h,i0): logits = Q*K^T/8 via 3-product bf16 mma; E = exp(logits);
// row sums -> sinv = 0.125/S; store E to P for causal tiles.
// ============================================================================
__global__ __launch_bounds__(256) void attn_exp(
    const bf16* __restrict__ qkh, const bf16* __restrict__ qkl,
    float* __restrict__ P, float* __restrict__ sinv)
{
    extern __shared__ uint32_t sm[];
    uint32_t* sQh = sm;
    uint32_t* sQl = sm + 128*36;
    uint32_t* sKh = sm + 2*128*36;
    uint32_t* sKl = sm + 3*128*36;
    __shared__ float sred[128];

    const int bh = blockIdx.x;
    const int ti = blockIdx.y;
    const int i0 = ti * 128;
    const int b  = bh >> 3, h = bh & 7;
    const size_t qoff = (size_t)(b*Lq)*1024 + h*64;

    const int t = threadIdx.x;
    const int lane = t & 31, wid = t >> 5;
    const int wm = wid >> 2, wn = wid & 3;
    const int gid = lane >> 2, tig = lane & 3;
    const int fr = t >> 1, half = t & 1;

    if (t < 128) sred[t] = 0.f;

    // load Q tile [128 x 64] (hi/lo bf16)
    {
        const uint4* sh = (const uint4*)(qkh + qoff + (size_t)(i0+fr)*1024 + half*32);
        const uint4* sl = (const uint4*)(qkl + qoff + (size_t)(i0+fr)*1024 + half*32);
        uint4* dh = (uint4*)(sQh + fr*36 + half*16);
        uint4* dl = (uint4*)(sQl + fr*36 + half*16);
        dh[0]=sh[0]; dh[1]=sh[1]; dh[2]=sh[2]; dh[3]=sh[3];
        dl[0]=sl[0]; dl[1]=sl[1]; dl[2]=sl[2]; dl[3]=sl[3];
    }

    float rsum[4][2];
    #pragma unroll
    for (int mi=0;mi<4;mi++){ rsum[mi][0]=0.f; rsum[mi][1]=0.f; }

    for (int jt = 0; jt < Lq/128; jt++){
        const int j0 = jt * 128;
        __syncthreads();
        {
            const uint4* sh = (const uint4*)(qkh + qoff + 512 + (size_t)(j0+fr)*1024 + half*32);
            const uint4* sl = (const uint4*)(qkl + qoff + 512 + (size_t)(j0+fr)*1024 + half*32);
            uint4* dh = (uint4*)(sKh + fr*36 + half*16);
            uint4* dl = (uint4*)(sKl + fr*36 + half*16);
            dh[0]=sh[0]; dh[1]=sh[1]; dh[2]=sh[2]; dh[3]=sh[3];
            dl[0]=sl[0]; dl[1]=sl[1]; dl[2]=sl[2]; dl[3]=sl[3];
        }
        __syncthreads();

        float acc[4][4][4];
        #pragma unroll
        for (int i=0;i<4;i++)
            #pragma unroll
            for (int j=0;j<4;j++)
                #pragma unroll
                for (int q=0;q<4;q++) acc[i][j][q] = 0.f;

        #pragma unroll
        for (int ks=0; ks<4; ks++){
            const int ci = tig + ks*8;
            uint32_t bhf[4][2], blf[4][2];
            #pragma unroll
            for (int ni=0;ni<4;ni++){
                int n = (wn*32 + ni*8 + gid)*36;
                bhf[ni][0] = sKh[n + ci];  bhf[ni][1] = sKh[n + ci + 4];
                blf[ni][0] = sKl[n + ci];  blf[ni][1] = sKl[n + ci + 4];
            }
            #pragma unroll
            for (int mi=0;mi<4;mi++){
                int m0 = (wm*64 + mi*16 + gid)*36;
                uint32_t ah[4] = {sQh[m0+ci], sQh[m0+288+ci], sQh[m0+ci+4], sQh[m0+288+ci+4]};
                uint32_t al[4] = {sQl[m0+ci], sQl[m0+288+ci], sQl[m0+ci+4], sQl[m0+288+ci+4]};
                #pragma unroll
                for (int ni=0;ni<4;ni++){
                    mma16816(acc[mi][ni], ah, bhf[ni]);
                    mma16816(acc[mi][ni], ah, blf[ni]);
                    mma16816(acc[mi][ni], al, bhf[ni]);
                }
            }
        }

        const bool store = (jt <= ti);
        #pragma unroll
        for (int mi=0;mi<4;mi++){
            const int row = i0 + wm*64 + mi*16 + gid;
            #pragma unroll
            for (int ni=0;ni<4;ni++){
                float e0 = __expf(acc[mi][ni][0] * 0.125f);
                float e1 = __expf(acc[mi][ni][1] * 0.125f);
                float e2 = __expf(acc[mi][ni][2] * 0.125f);
                float e3 = __expf(acc[mi][ni][3] * 0.125f);
                rsum[mi][0] += e0 + e1;
                rsum[mi][1] += e2 + e3;
                if (store){
                    const int col = j0 + wn*32 + ni*8 + tig*2;
                    float* p0 = P + ((size_t)bh*Lq + row)*Lq + col;
                    *(float2*)p0            = make_float2(e0, e1);
                    *(float2*)(p0 + 8*Lq)   = make_float2(e2, e3);
                }
            }
        }
    }

    #pragma unroll
    for (int mi=0;mi<4;mi++){
        float r0 = rsum[mi][0], r1 = rsum[mi][1];
        r0 += __shfl_xor_sync(0xffffffffu, r0, 1);
        r0 += __shfl_xor_sync(0xffffffffu, r0, 2);
        r1 += __shfl_xor_sync(0xffffffffu, r1, 1);
        r1 += __shfl_xor_sync(0xffffffffu, r1, 2);
        if (tig == 0){
            atomicAdd(&sred[wm*64 + mi*16 + gid    ], r0);
            atomicAdd(&sred[wm*64 + mi*16 + gid + 8], r1);
        }
    }
    __syncthreads();
    if (t < 128)
        sinv[(size_t)bh*Lq + i0 + t] = 0.125f / sred[t];
}

// ============================================================================
// A[b,i,j] = sum_h P[b,h,i,j] * sinv[b,h,i]   (causal tiles only)
// ============================================================================
__global__ __launch_bounds__(256) void attn_accum(
    const float* __restrict__ P, const float* __restrict__ sinv, float* __restrict__ A)
{
    const int tj = blockIdx.x, ti = blockIdx.y, b = blockIdx.z;
    if (tj > ti) return;
    const int i0 = ti*128, j0 = tj*128;
    __shared__ float ss[8][128];
    const int t = threadIdx.x;
    #pragma unroll
    for (int u=0;u<4;u++){
        int idx = t + u*256;
        int h = idx >> 7, r = idx & 127;
        ss[h][r] = sinv[((size_t)(b*Hq + h))*Lq + i0 + r];
    }
    __syncthreads();
    const size_t bs = (size_t)b*Hq*Lq*Lq;
    #pragma unroll
    for (int u=0;u<16;u++){
        int idx = t + u*256;
        int r = idx >> 5, c = (idx & 31)*4;
        float4 a = make_float4(0.f,0.f,0.f,0.f);
        #pragma unroll
        for (int h=0; h<8; h++){
            const float4 p = *(const float4*)(P + bs + ((size_t)h*Lq + i0 + r)*Lq + j0 + c);
            float s = ss[h][r];
            a.x = fmaf(p.x, s, a.x); a.y = fmaf(p.y, s, a.y);
            a.z = fmaf(p.z, s, a.z); a.w = fmaf(p.w, s, a.w);
        }
        *(float4*)(A + ((size_t)(b*Lq) + i0 + r)*Lq + j0 + c) = a;
    }
}

// ============================================================================
// W = softmax_j<=i ( A + exp(-(i-j)*0.1) ); writes split bf16 Wh/Wl.
// ============================================================================
__global__ __launch_bounds__(256) void make_w(
    const float* __restrict__ A, bf16* __restrict__ Wh, bf16* __restrict__ Wl)
{
    const int row = blockIdx.x;
    const int i   = row & (Lq-1);
    const float* a = A + (size_t)row * Lq;
    const int t = threadIdx.x;
    const int j0 = t*4;
    float4 av = *(const float4*)(a + j0);
    float v[4]; float s = 0.f;
    const float arr[4] = {av.x, av.y, av.z, av.w};
    #pragma unroll
    for (int u=0;u<4;u++){
        int j = j0 + u;
        float val = 0.f;
        if (j <= i){
            float pos = __expf((float)(j - i) * 0.1f);
            val = __expf(arr[u] + pos);
        }
        v[u] = val; s += val;
    }
    s = warp_sum(s);
    __shared__ float red[8];
    if ((t & 31) == 0) red[t >> 5] = s;
    __syncthreads();
    float tot = 0.f;
    #pragma unroll
    for (int w=0;w<8;w++) tot += red[w];
    float inv = 1.f / tot;
    uint32_t h0,l0,h1,l1;
    bsplit(v[0]*inv, v[1]*inv, h0, l0);
    bsplit(v[2]*inv, v[3]*inv, h1, l1);
    *(uint2*)(Wh + (size_t)row*Lq + j0) = make_uint2(h0, h1);
    *(uint2*)(Wl + (size_t)row*Lq + j0) = make_uint2(l0, l1);
}

// ============================================================================
// Batched transpose + split: xt[b][e][l] = split(x[b][l][e])
// ============================================================================
__global__ __launch_bounds__(256) void transpose_x(
    const float* __restrict__ x, bf16* __restrict__ xth, bf16* __restrict__ xtl)
{
    __shared__ float tile[32][33];
    const int b  = blockIdx.z;
    const int l0 = blockIdx.y * 32, e0 = blockIdx.x * 32;
    const float* xp = x + (size_t)b * Lq * Eq;
    const int tx = threadIdx.x, ty = threadIdx.y;
    #pragma unroll
    for (int j=0;j<32;j+=8)
        tile[ty+j][tx] = xp[(size_t)(l0+ty+j)*Eq + e0 + tx];
    __syncthreads();
    const size_t base = (size_t)b * Eq * Lq;
    #pragma unroll
    for (int j=0;j<32;j+=8){
        float v = tile[tx][ty+j];
        bf16 h = __float2bfloat16_rn(v);
        bf16 l = __float2bfloat16_rn(v - __bfloat162float(h));
        xth[base + (size_t)(e0+ty+j)*Lq + l0 + tx] = h;
        xtl[base + (size_t)(e0+ty+j)*Lq + l0 + tx] = l;
    }
}

// ============================================================================
// LayerNorm kernels (one warp per 512-wide row); optional split output
// ============================================================================
template<int SPLIT>
__global__ __launch_bounds__(256) void add_ln2(
    const float* __restrict__ x, const float* __restrict__ y,
    const float* __restrict__ g1, const float* __restrict__ b1,
    const float* __restrict__ g2, const float* __restrict__ b2,
    float* __restrict__ out, bf16* __restrict__ oh, bf16* __restrict__ ol)
{
    const int row  = blockIdx.x * 8 + (threadIdx.x >> 5);
    const int lane = threadIdx.x & 31;
    const float* xr = x + (size_t)row * Eq;
    const float* yr = y + (size_t)row * Eq;
    float v[16]; float s = 0.f;
    #pragma unroll
    for (int u=0;u<16;u++){ int c = lane + u*32; v[u] = xr[c] + yr[c]; s += v[u]; }
    s = warp_sum(s);
    float mean = s * (1.0f/Eq);
    float sq = 0.f;
    #pragma unroll
    for (int u=0;u<16;u++){ float d = v[u]-mean; sq += d*d; }
    sq = warp_sum(sq);
    float rstd = rsqrtf(sq*(1.0f/Eq) + 1e-5f);
    float s2 = 0.f;
    #pragma unroll
    for (int u=0;u<16;u++){ int c = lane + u*32; v[u] = (v[u]-mean)*rstd*g1[c] + b1[c]; s2 += v[u]; }
    s2 = warp_sum(s2);
    float m2 = s2 * (1.0f/Eq);
    float q2 = 0.f;
    #pragma unroll
    for (int u=0;u<16;u++){ float d = v[u]-m2; q2 += d*d; }
    q2 = warp_sum(q2);
    float r2 = rsqrtf(q2*(1.0f/Eq) + 1e-5f);
    float* orow = out + (size_t)row * Eq;
    #pragma unroll
    for (int u=0;u<16;u++){
        int c = lane + u*32;
        float o = (v[u]-m2)*r2*g2[c] + b2[c];
        orow[c] = o;
        if (SPLIT){
            bf16 h = __float2bfloat16_rn(o);
            oh[(size_t)row*Eq + c] = h;
            ol[(size_t)row*Eq + c] = __float2bfloat16_rn(o - __bfloat162float(h));
        }
    }
}

template<int SPLIT>
__global__ __launch_bounds__(256) void add_ln1(
    const float* __restrict__ x, const float* __restrict__ y,
    const float* __restrict__ g, const float* __restrict__ b,
    float* __restrict__ out, bf16* __restrict__ oh, bf16* __restrict__ ol)
{
    const int row  = blockIdx.x * 8 + (threadIdx.x >> 5);
    const int lane = threadIdx.x & 31;
    const float* xr = x + (size_t)row * Eq;
    const float* yr = y + (size_t)row * Eq;
    float v[16]; float s = 0.f;
    #pragma unroll
    for (int u=0;u<16;u++){ int c = lane + u*32; v[u] = xr[c] + yr[c]; s += v[u]; }
    s = warp_sum(s);
    float mean = s * (1.0f/Eq);
    float sq = 0.f;
    #pragma unroll
    for (int u=0;u<16;u++){ float d = v[u]-mean; sq += d*d; }
    sq = warp_sum(sq);
    float rstd = rsqrtf(sq*(1.0f/Eq) + 1e-5f);
    float* orow = out + (size_t)row * Eq;
    #pragma unroll
    for (int u=0;u<16;u++){
        int c = lane + u*32;
        float o = (v[u]-mean)*rstd*g[c] + b[c];
        orow[c] = o;
        if (SPLIT){
            bf16 h = __float2bfloat16_rn(o);
            oh[(size_t)row*Eq + c] = h;
            ol[(size_t)row*Eq + c] = __float2bfloat16_rn(o - __bfloat162float(h));
        }
    }
}

// ============================================================================
// Launch
// ============================================================================
extern "C" void kernel_launch(void* const* d_in, const int* in_sizes, int n_in,
                              void* d_out, int out_size)
{
    const float* input = (const float*)d_in[0];
    const float* Wqkv  = (const float*)d_in[1];
    const float* bqkv  = (const float*)d_in[2];
    const float* W1    = (const float*)d_in[3];
    const float* b1    = (const float*)d_in[4];
    const float* W2    = (const float*)d_in[5];
    const float* b2    = (const float*)d_in[6];
    const float* g1    = (const float*)d_in[7];
    const float* bt1   = (const float*)d_in[8];
    const float* g2    = (const float*)d_in[9];
    const float* bt2   = (const float*)d_in[10];
    const float* g3    = (const float*)d_in[11];
    const float* bt3   = (const float*)d_in[12];

    float *x, *sv, *A, *tb, *P;
    bf16 *xh,*xl,*qkh,*qkl,*awh,*awl,*xth,*xtl,*hh,*hl,*Wqh,*Wql,*W1h,*W1l,*W2h,*W2l;
    cudaGetSymbolAddress((void**)&x,  g_x);
    cudaGetSymbolAddress((void**)&sv, g_sv);
    cudaGetSymbolAddress((void**)&A,  g_A);
    cudaGetSymbolAddress((void**)&tb, g_t);
    cudaGetSymbolAddress((void**)&P,  g_P);
    cudaGetSymbolAddress((void**)&xh, g_xh);   cudaGetSymbolAddress((void**)&xl, g_xl);
    cudaGetSymbolAddress((void**)&qkh,g_qkh);  cudaGetSymbolAddress((void**)&qkl,g_qkl);
    cudaGetSymbolAddress((void**)&awh,g_awh);  cudaGetSymbolAddress((void**)&awl,g_awl);
    cudaGetSymbolAddress((void**)&xth,g_xth);  cudaGetSymbolAddress((void**)&xtl,g_xtl);
    cudaGetSymbolAddress((void**)&hh, g_hh);   cudaGetSymbolAddress((void**)&hl, g_hl);
    cudaGetSymbolAddress((void**)&Wqh,g_Wqh);  cudaGetSymbolAddress((void**)&Wql,g_Wql);
    cudaGetSymbolAddress((void**)&W1h,g_W1h);  cudaGetSymbolAddress((void**)&W1l,g_W1l);
    cudaGetSymbolAddress((void**)&W2h,g_W2h);  cudaGetSymbolAddress((void**)&W2l,g_W2l);

    const int ATTN_SMEM = 4 * 128 * 36 * 4;
    cudaFuncSetAttribute(attn_exp, cudaFuncAttributeMaxDynamicSharedMemorySize, ATTN_SMEM);

    // one-time splits (weights + input)
    for (int d = 0; d < 4; d++){
        int n4 = 1024*512/4;
        split_arr<<<(n4+255)/256, 256>>>(Wqkv + (size_t)d*1536*512,
                                         Wqh + (size_t)d*1024*512,
                                         Wql + (size_t)d*1024*512, n4);
    }
    {
        int n4 = 4*2048*512/4;
        split_arr<<<(n4+255)/256, 256>>>(W1, W1h, W1l, n4);
        split_arr<<<(n4+255)/256, 256>>>(W2, W2h, W2l, n4);
    }
    {
        int n4 = Mq*Eq/4;
        split_copy<<<(n4+255)/256, 256>>>(input, x, xh, xl, n4);
    }

    for (int d = 0; d < 4; d++){
        const float* bq = bqkv + (size_t)d * 1536;

        // q|k projection -> split qk (v/out-proj of Wqkv are dead in the reference)
        mma_gemm2<0,0,1><<<dim3(1024/128, Mq/128, 1), 256>>>(
            xh, xl, Wqh + (size_t)d*1024*512, Wql + (size_t)d*1024*512,
            bq, nullptr, qkh, qkl, Mq, 1024, 512, 0, 0, 0, 0);

        // fused tensor-core logits+exp (stores causal P, computes sinv)
        attn_exp<<<dim3(Bq*Hq, Lq/128), 256, ATTN_SMEM>>>(qkh, qkl, P, sv);

        // head-averaged A over causal tiles (memory-bound)
        attn_accum<<<dim3(Lq/128, Lq/128, Bq), 256>>>(P, sv, A);

        // second softmax with causal mask + pos bias -> split attention weights
        make_w<<<Bq*Lq, 256>>>(A, awh, awl);

        // sa = W @ x: split transpose of x, then NT GEMM w/ causal k cutoff
        transpose_x<<<dim3(Eq/32, Lq/32, Bq), dim3(32,8)>>>(x, xth, xtl);
        mma_gemm2<0,1,0><<<dim3(Eq/128, Lq/128, Bq), 256>>>(
            awh, awl, xth, xtl, nullptr, tb, nullptr, nullptr,
            Lq, Eq, Lq, (long)Lq*Lq, (long)Eq*Lq, (long)Lq*Eq, 1);

        // x = LN2(LN1(x + sa))  (cross-attn block is a double-LN no-op)
        add_ln2<1><<<Mq/8, 256>>>(x, tb,
                                  g1 + d*Eq, bt1 + d*Eq,
                                  g2 + d*Eq, bt2 + d*Eq, x, xh, xl);

        // FFN1 -> split h (relu), FFN2 -> fp32 tb
        mma_gemm2<1,0,1><<<dim3(FFq/128, Mq/128, 1), 256>>>(
            xh, xl, W1h + (size_t)d*2048*512, W1l + (size_t)d*2048*512,
            b1 + (size_t)d*FFq, nullptr, hh, hl, Mq, FFq, Eq, 0, 0, 0, 0);
        mma_gemm2<0,1,0><<<dim3(Eq/128, Mq/128, 1), 256>>>(
            hh, hl, W2h + (size_t)d*512*2048, W2l + (size_t)d*512*2048,
            b2 + (size_t)d*Eq, tb, nullptr, nullptr, Mq, Eq, FFq, 0, 0, 0, 0);

        if (d == 3)
            add_ln1<0><<<Mq/8, 256>>>(x, tb, g3 + d*Eq, bt3 + d*Eq,
                                      (float*)d_out, nullptr, nullptr);
        else
            add_ln1<1><<<Mq/8, 256>>>(x, tb, g3 + d*Eq, bt3 + d*Eq, x, xh, xl);
    }
}

// round 7
// speedup vs baseline: 1.3275x; 1.3275x over previous
#include <cuda_runtime.h>
#include <cuda_fp16.h>
#include <cuda_bf16.h>
#include <math.h>
#include <stdint.h>

// Problem constants
#define Bq   8
#define Lq   1024
#define Eq   512
#define Hq   8
#define FFq  2048
#define Mq   (Bq*Lq)          // 8192 tokens

typedef __half     fp16;
typedef __nv_bfloat16 bf16;

// ---------------- scratch (static device globals; allocation-free) ----------
__device__ float g_x [Mq*Eq];        // current activations (fp32, residual path)
__device__ float g_sv[Bq*Hq*Lq];     // per-(b,h,i) 0.125/sum(exp)
__device__ float g_A [Bq*Lq*Lq];     // head-avg attn (fp32, softmax2 input)
__device__ float g_t [Mq*Eq];        // sa / ff temp (fp32)
__device__ bf16  g_P [(size_t)Bq*Hq*Lq*Lq];  // per-head exp(logits), bf16, causal tiles

// fp16 split buffers: activations split (hi+lo), B-side operands plain (hi only)
__device__ fp16 g_xh [Mq*Eq],     g_xl [Mq*Eq];
__device__ fp16 g_qkh[Mq*1024],   g_qkl[Mq*1024];
__device__ fp16 g_awh[(size_t)Bq*Lq*Lq], g_awl[(size_t)Bq*Lq*Lq];
__device__ fp16 g_xt [Bq*Eq*Lq];
__device__ fp16 g_hh [Mq*FFq],    g_hl [Mq*FFq];
__device__ fp16 g_Wq [4*1024*512];
__device__ fp16 g_W1 [4*2048*512];
__device__ fp16 g_W2 [4*512*2048];

// ---------------- helpers ------------------------------------------------------
__device__ __forceinline__ float warp_sum(float s){
    #pragma unroll
    for (int o=16;o;o>>=1) s += __shfl_xor_sync(0xffffffffu, s, o);
    return s;
}

// split fp32 pair into packed fp16 hi + packed fp16 residual lo
__device__ __forceinline__ void hsplit(float x0, float x1, uint32_t& hi, uint32_t& lo){
    fp16 h0 = __float2half_rn(x0);
    fp16 h1 = __float2half_rn(x1);
    fp16 l0 = __float2half_rn(x0 - __half2float(h0));
    fp16 l1 = __float2half_rn(x1 - __half2float(h1));
    hi = (uint32_t)__half_as_ushort(h0) | ((uint32_t)__half_as_ushort(h1) << 16);
    lo = (uint32_t)__half_as_ushort(l0) | ((uint32_t)__half_as_ushort(l1) << 16);
}
__device__ __forceinline__ uint32_t hquant(float x0, float x1){
    return (uint32_t)__half_as_ushort(__float2half_rn(x0)) |
           ((uint32_t)__half_as_ushort(__float2half_rn(x1)) << 16);
}
__device__ __forceinline__ uint32_t bpack(float x0, float x1){
    __nv_bfloat162 b = __floats2bfloat162_rn(x0, x1);
    return *(uint32_t*)&b;
}

__device__ __forceinline__ void mma16816(float* c, const uint32_t* a, const uint32_t* b){
    asm volatile(
        "mma.sync.aligned.m16n8k16.row.col.f32.f16.f16.f32 "
        "{%0,%1,%2,%3}, {%4,%5,%6,%7}, {%8,%9}, {%0,%1,%2,%3};\n"
        : "+f"(c[0]), "+f"(c[1]), "+f"(c[2]), "+f"(c[3])
        : "r"(a[0]), "r"(a[1]), "r"(a[2]), "r"(a[3]), "r"(b[0]), "r"(b[1]));
}

// ============================================================================
// Weight quantization / input split kernels
// ============================================================================
__global__ __launch_bounds__(256) void quant_arr(
    const float* __restrict__ in, fp16* __restrict__ oh, int n4)
{
    int i = blockIdx.x*256 + threadIdx.x;
    if (i >= n4) return;
    float4 v = ((const float4*)in)[i];
    ((uint2*)oh)[i] = make_uint2(hquant(v.x, v.y), hquant(v.z, v.w));
}

__global__ __launch_bounds__(256) void split_copy(
    const float* __restrict__ in, float* __restrict__ out,
    fp16* __restrict__ oh, fp16* __restrict__ ol, int n4)
{
    int i = blockIdx.x*256 + threadIdx.x;
    if (i >= n4) return;
    float4 v = ((const float4*)in)[i];
    ((float4*)out)[i] = v;
    uint32_t h0,l0,h1,l1;
    hsplit(v.x, v.y, h0, l0);
    hsplit(v.z, v.w, h1, l1);
    ((uint2*)oh)[i] = make_uint2(h0, h1);
    ((uint2*)ol)[i] = make_uint2(l0, l1);
}

// ============================================================================
// Tensor-core GEMM NT, fp16 2-product (A exactly split, B fp16-quantized):
//   C[M,N] = (Ah+Al)[M,K] * Bh[N,K]^T (+bias, relu), batched via z.
// Block tile 128x128, BK=32, 256 threads (2x4 warps, 64x32 each).
// ============================================================================
template<int RELU, int WF32, int WSPLIT>
__global__ __launch_bounds__(256, 2) void mma_gemm2(
    const fp16* __restrict__ Ah, const fp16* __restrict__ Al,
    const fp16* __restrict__ Bh,
    const float* __restrict__ bias,
    float* __restrict__ C, fp16* __restrict__ Ch, fp16* __restrict__ Cl,
    int M, int N, int K, long sA, long sB, long sC, int causal)
{
    __shared__ uint32_t sAh[128*20], sAl[128*20], sBh[128*20];
    const int bm = blockIdx.y * 128, bn = blockIdx.x * 128;
    const fp16* Abh = Ah + (size_t)blockIdx.z * sA;
    const fp16* Abl = Al + (size_t)blockIdx.z * sA;
    const fp16* Bbh = Bh + (size_t)blockIdx.z * sB;

    const int t    = threadIdx.x;
    const int lane = t & 31, wid = t >> 5;
    const int wm   = wid >> 2, wn = wid & 3;
    const int gid  = lane >> 2, tig = lane & 3;

    float acc[4][4][4];
    #pragma unroll
    for (int i=0;i<4;i++)
        #pragma unroll
        for (int j=0;j<4;j++)
            #pragma unroll
            for (int q=0;q<4;q++) acc[i][j][q] = 0.f;

    const int fr = t >> 1, half = t & 1;
    const uint4* A4h = (const uint4*)(Abh + (size_t)(bm+fr)*K);
    const uint4* A4l = (const uint4*)(Abl + (size_t)(bm+fr)*K);
    const uint4* B4h = (const uint4*)(Bbh + (size_t)(bn+fr)*K);
    uint4* dAh = (uint4*)(sAh + fr*20 + half*8);
    uint4* dAl = (uint4*)(sAl + fr*20 + half*8);
    uint4* dBh = (uint4*)(sBh + fr*20 + half*8);

    const int kend = causal ? (bm + 128) : K;
    for (int k0 = 0; k0 < kend; k0 += 32){
        const int gi = (k0 >> 3) + half*2;          // uint4 index (8 fp16 each)
        uint4 vah0 = A4h[gi], vah1 = A4h[gi+1];
        uint4 val0 = A4l[gi], val1 = A4l[gi+1];
        uint4 vbh0 = B4h[gi], vbh1 = B4h[gi+1];
        __syncthreads();
        dAh[0] = vah0; dAh[1] = vah1;
        dAl[0] = val0; dAl[1] = val1;
        dBh[0] = vbh0; dBh[1] = vbh1;
        __syncthreads();

        #pragma unroll
        for (int ks=0; ks<2; ks++){
            const int ci = tig + ks*8;
            uint32_t bhf[4][2];
            #pragma unroll
            for (int ni=0;ni<4;ni++){
                int n = (wn*32 + ni*8 + gid)*20;
                bhf[ni][0] = sBh[n + ci];  bhf[ni][1] = sBh[n + ci + 4];
            }
            #pragma unroll
            for (int mi=0;mi<4;mi++){
                int m0 = (wm*64 + mi*16 + gid)*20;
                uint32_t ah[4] = {sAh[m0+ci], sAh[m0+160+ci], sAh[m0+ci+4], sAh[m0+160+ci+4]};
                uint32_t al[4] = {sAl[m0+ci], sAl[m0+160+ci], sAl[m0+ci+4], sAl[m0+160+ci+4]};
                #pragma unroll
                for (int ni=0;ni<4;ni++){
                    mma16816(acc[mi][ni], ah, bhf[ni]);
                    mma16816(acc[mi][ni], al, bhf[ni]);
                }
            }
        }
    }

    float* Cb  = WF32   ? C  + (size_t)blockIdx.z * sC : nullptr;
    fp16*  Chb = WSPLIT ? Ch + (size_t)blockIdx.z * sC : nullptr;
    fp16*  Clb = WSPLIT ? Cl + (size_t)blockIdx.z * sC : nullptr;
    #pragma unroll
    for (int mi=0;mi<4;mi++){
        int row = bm + wm*64 + mi*16 + gid;
        #pragma unroll
        for (int ni=0;ni<4;ni++){
            int col = bn + wn*32 + ni*8 + tig*2;
            float2 v0 = make_float2(acc[mi][ni][0], acc[mi][ni][1]);
            float2 v1 = make_float2(acc[mi][ni][2], acc[mi][ni][3]);
            if (bias){
                float2 bb = *(const float2*)(bias + col);
                v0.x += bb.x; v0.y += bb.y; v1.x += bb.x; v1.y += bb.y;
            }
            if (RELU){
                v0.x=fmaxf(v0.x,0.f); v0.y=fmaxf(v0.y,0.f);
                v1.x=fmaxf(v1.x,0.f); v1.y=fmaxf(v1.y,0.f);
            }
            if (WF32){
                *(float2*)(Cb + (size_t)row    *N + col) = v0;
                *(float2*)(Cb + (size_t)(row+8)*N + col) = v1;
            }
            if (WSPLIT){
                uint32_t h0,l0,h1,l1;
                hsplit(v0.x, v0.y, h0, l0);
                hsplit(v1.x, v1.y, h1, l1);
                *(uint32_t*)(Chb + (size_t)row    *N + col) = h0;
                *(uint32_t*)(Clb + (size_t)row    *N + col) = l0;
                *(uint32_t*)(Chb + (size_t)(row+8)*N + col) = h1;
                *(uint32_t*)(Clb + (size_t)(row+8)*N + col) = l1;
            }
        }
    }
}

// ============================================================================
// Fused attention exp kernel, fp16 2-product (Q split, K fp16-quantized):
// per (b,h,i0): logits = (Qh+Ql)*Kh^T/8; E = exp; row sums -> sinv;
// store E (bf16) to P for causal tiles.
// ============================================================================
#define ATTN_SMEM (3*128*36*4)
__global__ __launch_bounds__(256) void attn_exp(
    const fp16* __restrict__ qkh, const fp16* __restrict__ qkl,
    bf16* __restrict__ P, float* __restrict__ sinv)
{
    extern __shared__ uint32_t smx[];
    uint32_t* sQh = smx;
    uint32_t* sQl = smx + 128*36;
    uint32_t* sKh = smx + 2*128*36;
    __shared__ float sred[128];

    const int bh = blockIdx.x;
    const int ti = blockIdx.y;
    const int i0 = ti * 128;
    const int b  = bh >> 3, h = bh & 7;
    const size_t qoff = (size_t)(b*Lq)*1024 + h*64;

    const int t = threadIdx.x;
    const int lane = t & 31, wid = t >> 5;
    const int wm = wid >> 2, wn = wid & 3;
    const int gid = lane >> 2, tig = lane & 3;
    const int fr = t >> 1, half = t & 1;

    if (t < 128) sred[t] = 0.f;

    // load Q tile [128 x 64] hi/lo
    {
        const uint4* sh = (const uint4*)(qkh + qoff + (size_t)(i0+fr)*1024 + half*32);
        const uint4* sl = (const uint4*)(qkl + qoff + (size_t)(i0+fr)*1024 + half*32);
        uint4* dh = (uint4*)(sQh + fr*36 + half*16);
        uint4* dl = (uint4*)(sQl + fr*36 + half*16);
        dh[0]=sh[0]; dh[1]=sh[1]; dh[2]=sh[2]; dh[3]=sh[3];
        dl[0]=sl[0]; dl[1]=sl[1]; dl[2]=sl[2]; dl[3]=sl[3];
    }

    float rsum[4][2];
    #pragma unroll
    for (int mi=0;mi<4;mi++){ rsum[mi][0]=0.f; rsum[mi][1]=0.f; }

    for (int jt = 0; jt < Lq/128; jt++){
        const int j0 = jt * 128;
        __syncthreads();
        {   // K tile [128 x 64], hi only
            const uint4* sh = (const uint4*)(qkh + qoff + 512 + (size_t)(j0+fr)*1024 + half*32);
            uint4* dh = (uint4*)(sKh + fr*36 + half*16);
            dh[0]=sh[0]; dh[1]=sh[1]; dh[2]=sh[2]; dh[3]=sh[3];
        }
        __syncthreads();

        float acc[4][4][4];
        #pragma unroll
        for (int i=0;i<4;i++)
            #pragma unroll
            for (int j=0;j<4;j++)
                #pragma unroll
                for (int q=0;q<4;q++) acc[i][j][q] = 0.f;

        #pragma unroll
        for (int ks=0; ks<4; ks++){
            const int ci = tig + ks*8;
            uint32_t bhf[4][2];
            #pragma unroll
            for (int ni=0;ni<4;ni++){
                int n = (wn*32 + ni*8 + gid)*36;
                bhf[ni][0] = sKh[n + ci];  bhf[ni][1] = sKh[n + ci + 4];
            }
            #pragma unroll
            for (int mi=0;mi<4;mi++){
                int m0 = (wm*64 + mi*16 + gid)*36;
                uint32_t ah[4] = {sQh[m0+ci], sQh[m0+288+ci], sQh[m0+ci+4], sQh[m0+288+ci+4]};
                uint32_t al[4] = {sQl[m0+ci], sQl[m0+288+ci], sQl[m0+ci+4], sQl[m0+288+ci+4]};
                #pragma unroll
                for (int ni=0;ni<4;ni++){
                    mma16816(acc[mi][ni], ah, bhf[ni]);
                    mma16816(acc[mi][ni], al, bhf[ni]);
                }
            }
        }

        const bool store = (jt <= ti);
        #pragma unroll
        for (int mi=0;mi<4;mi++){
            const int row = i0 + wm*64 + mi*16 + gid;
            #pragma unroll
            for (int ni=0;ni<4;ni++){
                float e0 = __expf(acc[mi][ni][0] * 0.125f);
                float e1 = __expf(acc[mi][ni][1] * 0.125f);
                float e2 = __expf(acc[mi][ni][2] * 0.125f);
                float e3 = __expf(acc[mi][ni][3] * 0.125f);
                rsum[mi][0] += e0 + e1;
                rsum[mi][1] += e2 + e3;
                if (store){
                    const int col = j0 + wn*32 + ni*8 + tig*2;
                    bf16* p0 = P + ((size_t)bh*Lq + row)*Lq + col;
                    *(uint32_t*)p0          = bpack(e0, e1);
                    *(uint32_t*)(p0 + 8*Lq) = bpack(e2, e3);
                }
            }
        }
    }

    #pragma unroll
    for (int mi=0;mi<4;mi++){
        float r0 = rsum[mi][0], r1 = rsum[mi][1];
        r0 += __shfl_xor_sync(0xffffffffu, r0, 1);
        r0 += __shfl_xor_sync(0xffffffffu, r0, 2);
        r1 += __shfl_xor_sync(0xffffffffu, r1, 1);
        r1 += __shfl_xor_sync(0xffffffffu, r1, 2);
        if (tig == 0){
            atomicAdd(&sred[wm*64 + mi*16 + gid    ], r0);
            atomicAdd(&sred[wm*64 + mi*16 + gid + 8], r1);
        }
    }
    __syncthreads();
    if (t < 128)
        sinv[(size_t)bh*Lq + i0 + t] = 0.125f / sred[t];
}

// ============================================================================
// A[b,i,j] = sum_h P[b,h,i,j] * sinv[b,h,i]   (causal tiles only; bf16 P)
// ============================================================================
__global__ __launch_bounds__(256) void attn_accum(
    const bf16* __restrict__ P, const float* __restrict__ sinv, float* __restrict__ A)
{
    const int tj = blockIdx.x, ti = blockIdx.y, b = blockIdx.z;
    if (tj > ti) return;
    const int i0 = ti*128, j0 = tj*128;
    __shared__ float ss[8][128];
    const int t = threadIdx.x;
    #pragma unroll
    for (int u=0;u<4;u++){
        int idx = t + u*256;
        int h = idx >> 7, r = idx & 127;
        ss[h][r] = sinv[((size_t)(b*Hq + h))*Lq + i0 + r];
    }
    __syncthreads();
    const size_t bs = (size_t)b*Hq*Lq*Lq;
    #pragma unroll
    for (int u=0;u<8;u++){
        int idx = t + u*256;
        int r = idx >> 4, c = (idx & 15)*8;
        float a[8];
        #pragma unroll
        for (int q=0;q<8;q++) a[q] = 0.f;
        #pragma unroll
        for (int h=0; h<8; h++){
            const uint4 pv = *(const uint4*)(P + bs + ((size_t)h*Lq + i0 + r)*Lq + j0 + c);
            const float s = ss[h][r];
            float2 f0 = __bfloat1622float2(*(const __nv_bfloat162*)&pv.x);
            float2 f1 = __bfloat1622float2(*(const __nv_bfloat162*)&pv.y);
            float2 f2 = __bfloat1622float2(*(const __nv_bfloat162*)&pv.z);
            float2 f3 = __bfloat1622float2(*(const __nv_bfloat162*)&pv.w);
            a[0]=fmaf(f0.x,s,a[0]); a[1]=fmaf(f0.y,s,a[1]);
            a[2]=fmaf(f1.x,s,a[2]); a[3]=fmaf(f1.y,s,a[3]);
            a[4]=fmaf(f2.x,s,a[4]); a[5]=fmaf(f2.y,s,a[5]);
            a[6]=fmaf(f3.x,s,a[6]); a[7]=fmaf(f3.y,s,a[7]);
        }
        float* dst = A + ((size_t)(b*Lq) + i0 + r)*Lq + j0 + c;
        *(float4*)dst     = make_float4(a[0],a[1],a[2],a[3]);
        *(float4*)(dst+4) = make_float4(a[4],a[5],a[6],a[7]);
    }
}

// ============================================================================
// W = softmax_j<=i ( A + exp(-(i-j)*0.1) ); writes split fp16 Wh/Wl.
// ============================================================================
__global__ __launch_bounds__(256) void make_w(
    const float* __restrict__ A, fp16* __restrict__ Wh, fp16* __restrict__ Wl)
{
    const int row = blockIdx.x;
    const int i   = row & (Lq-1);
    const float* a = A + (size_t)row * Lq;
    const int t = threadIdx.x;
    const int j0 = t*4;
    float4 av = *(const float4*)(a + j0);
    float v[4]; float s = 0.f;
    const float arr[4] = {av.x, av.y, av.z, av.w};
    #pragma unroll
    for (int u=0;u<4;u++){
        int j = j0 + u;
        float val = 0.f;
        if (j <= i){
            float pos = __expf((float)(j - i) * 0.1f);
            val = __expf(arr[u] + pos);
        }
        v[u] = val; s += val;
    }
    s = warp_sum(s);
    __shared__ float red[8];
    if ((t & 31) == 0) red[t >> 5] = s;
    __syncthreads();
    float tot = 0.f;
    #pragma unroll
    for (int w=0;w<8;w++) tot += red[w];
    float inv = 1.f / tot;
    uint32_t h0,l0,h1,l1;
    hsplit(v[0]*inv, v[1]*inv, h0, l0);
    hsplit(v[2]*inv, v[3]*inv, h1, l1);
    *(uint2*)(Wh + (size_t)row*Lq + j0) = make_uint2(h0, h1);
    *(uint2*)(Wl + (size_t)row*Lq + j0) = make_uint2(l0, l1);
}

// ============================================================================
// Batched transpose + quantize: xt[b][e][l] = fp16(x[b][l][e])
// ============================================================================
__global__ __launch_bounds__(256) void transpose_x(
    const float* __restrict__ x, fp16* __restrict__ xt)
{
    __shared__ float tile[32][33];
    const int b  = blockIdx.z;
    const int l0 = blockIdx.y * 32, e0 = blockIdx.x * 32;
    const float* xp = x + (size_t)b * Lq * Eq;
    const int tx = threadIdx.x, ty = threadIdx.y;
    #pragma unroll
    for (int j=0;j<32;j+=8)
        tile[ty+j][tx] = xp[(size_t)(l0+ty+j)*Eq + e0 + tx];
    __syncthreads();
    const size_t base = (size_t)b * Eq * Lq;
    #pragma unroll
    for (int j=0;j<32;j+=8)
        xt[base + (size_t)(e0+ty+j)*Lq + l0 + tx] = __float2half_rn(tile[tx][ty+j]);
}

// ============================================================================
// LayerNorm kernels (one warp per 512-wide row); optional fp16 split output
// ============================================================================
template<int SPLIT>
__global__ __launch_bounds__(256) void add_ln2(
    const float* __restrict__ x, const float* __restrict__ y,
    const float* __restrict__ g1, const float* __restrict__ b1,
    const float* __restrict__ g2, const float* __restrict__ b2,
    float* __restrict__ out, fp16* __restrict__ oh, fp16* __restrict__ ol)
{
    const int row  = blockIdx.x * 8 + (threadIdx.x >> 5);
    const int lane = threadIdx.x & 31;
    const float* xr = x + (size_t)row * Eq;
    const float* yr = y + (size_t)row * Eq;
    float v[16]; float s = 0.f;
    #pragma unroll
    for (int u=0;u<16;u++){ int c = lane + u*32; v[u] = xr[c] + yr[c]; s += v[u]; }
    s = warp_sum(s);
    float mean = s * (1.0f/Eq);
    float sq = 0.f;
    #pragma unroll
    for (int u=0;u<16;u++){ float d = v[u]-mean; sq += d*d; }
    sq = warp_sum(sq);
    float rstd = rsqrtf(sq*(1.0f/Eq) + 1e-5f);
    float s2 = 0.f;
    #pragma unroll
    for (int u=0;u<16;u++){ int c = lane + u*32; v[u] = (v[u]-mean)*rstd*g1[c] + b1[c]; s2 += v[u]; }
    s2 = warp_sum(s2);
    float m2 = s2 * (1.0f/Eq);
    float q2 = 0.f;
    #pragma unroll
    for (int u=0;u<16;u++){ float d = v[u]-m2; q2 += d*d; }
    q2 = warp_sum(q2);
    float r2 = rsqrtf(q2*(1.0f/Eq) + 1e-5f);
    float* orow = out + (size_t)row * Eq;
    #pragma unroll
    for (int u=0;u<16;u++){
        int c = lane + u*32;
        float o = (v[u]-m2)*r2*g2[c] + b2[c];
        orow[c] = o;
        if (SPLIT){
            fp16 h = __float2half_rn(o);
            oh[(size_t)row*Eq + c] = h;
            ol[(size_t)row*Eq + c] = __float2half_rn(o - __half2float(h));
        }
    }
}

template<int SPLIT>
__global__ __launch_bounds__(256) void add_ln1(
    const float* __restrict__ x, const float* __restrict__ y,
    const float* __restrict__ g, const float* __restrict__ b,
    float* __restrict__ out, fp16* __restrict__ oh, fp16* __restrict__ ol)
{
    const int row  = blockIdx.x * 8 + (threadIdx.x >> 5);
    const int lane = threadIdx.x & 31;
    const float* xr = x + (size_t)row * Eq;
    const float* yr = y + (size_t)row * Eq;
    float v[16]; float s = 0.f;
    #pragma unroll
    for (int u=0;u<16;u++){ int c = lane + u*32; v[u] = xr[c] + yr[c]; s += v[u]; }
    s = warp_sum(s);
    float mean = s * (1.0f/Eq);
    float sq = 0.f;
    #pragma unroll
    for (int u=0;u<16;u++){ float d = v[u]-mean; sq += d*d; }
    sq = warp_sum(sq);
    float rstd = rsqrtf(sq*(1.0f/Eq) + 1e-5f);
    float* orow = out + (size_t)row * Eq;
    #pragma unroll
    for (int u=0;u<16;u++){
        int c = lane + u*32;
        float o = (v[u]-mean)*rstd*g[c] + b[c];
        orow[c] = o;
        if (SPLIT){
            fp16 h = __float2half_rn(o);
            oh[(size_t)row*Eq + c] = h;
            ol[(size_t)row*Eq + c] = __float2half_rn(o - __half2float(h));
        }
    }
}

// ============================================================================
// Launch
// ============================================================================
extern "C" void kernel_launch(void* const* d_in, const int* in_sizes, int n_in,
                              void* d_out, int out_size)
{
    const float* input = (const float*)d_in[0];
    const float* Wqkv  = (const float*)d_in[1];
    const float* bqkv  = (const float*)d_in[2];
    const float* W1    = (const float*)d_in[3];
    const float* b1    = (const float*)d_in[4];
    const float* W2    = (const float*)d_in[5];
    const float* b2    = (const float*)d_in[6];
    const float* g1    = (const float*)d_in[7];
    const float* bt1   = (const float*)d_in[8];
    const float* g2    = (const float*)d_in[9];
    const float* bt2   = (const float*)d_in[10];
    const float* g3    = (const float*)d_in[11];
    const float* bt3   = (const float*)d_in[12];

    float *x, *sv, *A, *tb;
    bf16 *P;
    fp16 *xh,*xl,*qkh,*qkl,*awh,*awl,*xt,*hh,*hl,*Wq,*W1f,*W2f;
    cudaGetSymbolAddress((void**)&x,  g_x);
    cudaGetSymbolAddress((void**)&sv, g_sv);
    cudaGetSymbolAddress((void**)&A,  g_A);
    cudaGetSymbolAddress((void**)&tb, g_t);
    cudaGetSymbolAddress((void**)&P,  g_P);
    cudaGetSymbolAddress((void**)&xh, g_xh);   cudaGetSymbolAddress((void**)&xl, g_xl);
    cudaGetSymbolAddress((void**)&qkh,g_qkh);  cudaGetSymbolAddress((void**)&qkl,g_qkl);
    cudaGetSymbolAddress((void**)&awh,g_awh);  cudaGetSymbolAddress((void**)&awl,g_awl);
    cudaGetSymbolAddress((void**)&xt, g_xt);
    cudaGetSymbolAddress((void**)&hh, g_hh);   cudaGetSymbolAddress((void**)&hl, g_hl);
    cudaGetSymbolAddress((void**)&Wq, g_Wq);
    cudaGetSymbolAddress((void**)&W1f,g_W1);
    cudaGetSymbolAddress((void**)&W2f,g_W2);

    cudaFuncSetAttribute(attn_exp, cudaFuncAttributeMaxDynamicSharedMemorySize, ATTN_SMEM);

    // one-time weight quantization + input split
    for (int d = 0; d < 4; d++){
        int n4 = 1024*512/4;
        quant_arr<<<(n4+255)/256, 256>>>(Wqkv + (size_t)d*1536*512,
                                         Wq + (size_t)d*1024*512, n4);
    }
    {
        int n4 = 4*2048*512/4;
        quant_arr<<<(n4+255)/256, 256>>>(W1, W1f, n4);
        quant_arr<<<(n4+255)/256, 256>>>(W2, W2f, n4);
    }
    {
        int n4 = Mq*Eq/4;
        split_copy<<<(n4+255)/256, 256>>>(input, x, xh, xl, n4);
    }

    for (int d = 0; d < 4; d++){
        const float* bq = bqkv + (size_t)d * 1536;

        // q|k projection -> split qk (v/out-proj of Wqkv are dead in the reference)
        mma_gemm2<0,0,1><<<dim3(1024/128, Mq/128, 1), 256>>>(
            xh, xl, Wq + (size_t)d*1024*512,
            bq, nullptr, qkh, qkl, Mq, 1024, 512, 0, 0, 0, 0);

        // fused logits+exp (stores causal bf16 P, computes sinv)
        attn_exp<<<dim3(Bq*Hq, Lq/128), 256, ATTN_SMEM>>>(qkh, qkl, P, sv);

        // head-averaged A over causal tiles (memory-bound)
        attn_accum<<<dim3(Lq/128, Lq/128, Bq), 256>>>(P, sv, A);

        // second softmax with causal mask + pos bias -> split fp16 attention weights
        make_w<<<Bq*Lq, 256>>>(A, awh, awl);

        // sa = W @ x: fp16 transpose of x, then NT GEMM w/ causal k cutoff
        transpose_x<<<dim3(Eq/32, Lq/32, Bq), dim3(32,8)>>>(x, xt);
        mma_gemm2<0,1,0><<<dim3(Eq/128, Lq/128, Bq), 256>>>(
            awh, awl, xt, nullptr, tb, nullptr, nullptr,
            Lq, Eq, Lq, (long)Lq*Lq, (long)Eq*Lq, (long)Lq*Eq, 1);

        // x = LN2(LN1(x + sa))  (cross-attn block is a double-LN no-op)
        add_ln2<1><<<Mq/8, 256>>>(x, tb,
                                  g1 + d*Eq, bt1 + d*Eq,
                                  g2 + d*Eq, bt2 + d*Eq, x, xh, xl);

        // FFN1 -> split h (relu), FFN2 -> fp32 tb
        mma_gemm2<1,0,1><<<dim3(FFq/128, Mq/128, 1), 256>>>(
            xh, xl, W1f + (size_t)d*2048*512,
            b1 + (size_t)d*FFq, nullptr, hh, hl, Mq, FFq, Eq, 0, 0, 0, 0);
        mma_gemm2<0,1,0><<<dim3(Eq/128, Mq/128, 1), 256>>>(
            hh, hl, W2f + (size_t)d*512*2048,
            b2 + (size_t)d*Eq, tb, nullptr, nullptr, Mq, Eq, FFq, 0, 0, 0, 0);

        if (d == 3)
            add_ln1<0><<<Mq/8, 256>>>(x, tb, g3 + d*Eq, bt3 + d*Eq,
                                      (float*)d_out, nullptr, nullptr);
        else
            add_ln1<1><<<Mq/8, 256>>>(x, tb, g3 + d*Eq, bt3 + d*Eq, x, xh, xl);
    }
}

// round 8
// speedup vs baseline: 1.9707x; 1.4846x over previous
#include <cuda_runtime.h>
#include <cuda_fp16.h>
#include <cuda_bf16.h>
#include <math.h>
#include <stdint.h>

// Problem constants
#define Bq   8
#define Lq   1024
#define Eq   512
#define Hq   8
#define FFq  2048
#define Mq   (Bq*Lq)          // 8192 tokens

typedef __half        fp16;
typedef __nv_bfloat16 bf16;

// ---------------- scratch (static device globals; allocation-free) ----------
__device__ float g_x [Mq*Eq];        // current activations (fp32, residual path)
__device__ float g_sv[Bq*Hq*Lq];     // per-(b,h,i) 0.125/sum(exp)
__device__ float g_A [Bq*Lq*Lq];     // head-avg attn (fp32, softmax2 input)
__device__ float g_t [Mq*Eq];        // sa / ff temp (fp32)
__device__ bf16  g_P [(size_t)Bq*Hq*Lq*Lq];  // per-head exp(logits), bf16, causal tiles

// fp16 buffers (plain quantized)
__device__ fp16 g_xh [Mq*Eq];
__device__ fp16 g_qk [Mq*1024];
__device__ fp16 g_aw [(size_t)Bq*Lq*Lq];
__device__ fp16 g_xt [Bq*Eq*Lq];
__device__ fp16 g_h  [Mq*FFq];
__device__ fp16 g_Wq [4*1024*512];
__device__ fp16 g_W1 [4*2048*512];
__device__ fp16 g_W2 [4*512*2048];

// ---------------- helpers ------------------------------------------------------
__device__ __forceinline__ float warp_sum(float s){
    #pragma unroll
    for (int o=16;o;o>>=1) s += __shfl_xor_sync(0xffffffffu, s, o);
    return s;
}
__device__ __forceinline__ uint32_t hquant(float x0, float x1){
    return (uint32_t)__half_as_ushort(__float2half_rn(x0)) |
           ((uint32_t)__half_as_ushort(__float2half_rn(x1)) << 16);
}
__device__ __forceinline__ uint32_t bpack(float x0, float x1){
    __nv_bfloat162 b = __floats2bfloat162_rn(x0, x1);
    return *(uint32_t*)&b;
}
__device__ __forceinline__ void mma16816(float* c, const uint32_t* a, const uint32_t* b){
    asm volatile(
        "mma.sync.aligned.m16n8k16.row.col.f32.f16.f16.f32 "
        "{%0,%1,%2,%3}, {%4,%5,%6,%7}, {%8,%9}, {%0,%1,%2,%3};\n"
        : "+f"(c[0]), "+f"(c[1]), "+f"(c[2]), "+f"(c[3])
        : "r"(a[0]), "r"(a[1]), "r"(a[2]), "r"(a[3]), "r"(b[0]), "r"(b[1]));
}

// ============================================================================
// Quantization kernels: fp32 -> fp16 (optionally keep fp32 copy)
// ============================================================================
__global__ __launch_bounds__(256) void quant_arr(
    const float* __restrict__ in, fp16* __restrict__ oh, int n4)
{
    int i = blockIdx.x*256 + threadIdx.x;
    if (i >= n4) return;
    float4 v = ((const float4*)in)[i];
    ((uint2*)oh)[i] = make_uint2(hquant(v.x, v.y), hquant(v.z, v.w));
}

__global__ __launch_bounds__(256) void quant_copy(
    const float* __restrict__ in, float* __restrict__ out,
    fp16* __restrict__ oh, int n4)
{
    int i = blockIdx.x*256 + threadIdx.x;
    if (i >= n4) return;
    float4 v = ((const float4*)in)[i];
    ((float4*)out)[i] = v;
    ((uint2*)oh)[i] = make_uint2(hquant(v.x, v.y), hquant(v.z, v.w));
}

// ============================================================================
// Tensor-core GEMM NT, plain fp16 x fp16, fp32 accumulate:
//   C[M,N] = A[M,K] * B[N,K]^T (+bias, relu), batched via z.
// Block tile 128x128, BK=32, 256 threads (2x4 warps, 64x32 each).
// ============================================================================
template<int RELU, int WF32, int WH16>
__global__ __launch_bounds__(256, 2) void mma_gemm2(
    const fp16* __restrict__ Ah, const fp16* __restrict__ Bh,
    const float* __restrict__ bias,
    float* __restrict__ C, fp16* __restrict__ Ch,
    int M, int N, int K, long sA, long sB, long sC, int causal)
{
    __shared__ uint32_t sAh[128*20], sBh[128*20];
    const int bm = blockIdx.y * 128, bn = blockIdx.x * 128;
    const fp16* Abh = Ah + (size_t)blockIdx.z * sA;
    const fp16* Bbh = Bh + (size_t)blockIdx.z * sB;

    const int t    = threadIdx.x;
    const int lane = t & 31, wid = t >> 5;
    const int wm   = wid >> 2, wn = wid & 3;
    const int gid  = lane >> 2, tig = lane & 3;

    float acc[4][4][4];
    #pragma unroll
    for (int i=0;i<4;i++)
        #pragma unroll
        for (int j=0;j<4;j++)
            #pragma unroll
            for (int q=0;q<4;q++) acc[i][j][q] = 0.f;

    const int fr = t >> 1, half = t & 1;
    const uint4* A4h = (const uint4*)(Abh + (size_t)(bm+fr)*K);
    const uint4* B4h = (const uint4*)(Bbh + (size_t)(bn+fr)*K);
    uint4* dAh = (uint4*)(sAh + fr*20 + half*8);
    uint4* dBh = (uint4*)(sBh + fr*20 + half*8);

    const int kend = causal ? (bm + 128) : K;
    for (int k0 = 0; k0 < kend; k0 += 32){
        const int gi = (k0 >> 3) + half*2;          // uint4 index (8 fp16 each)
        uint4 vah0 = A4h[gi], vah1 = A4h[gi+1];
        uint4 vbh0 = B4h[gi], vbh1 = B4h[gi+1];
        __syncthreads();
        dAh[0] = vah0; dAh[1] = vah1;
        dBh[0] = vbh0; dBh[1] = vbh1;
        __syncthreads();

        #pragma unroll
        for (int ks=0; ks<2; ks++){
            const int ci = tig + ks*8;
            uint32_t bhf[4][2];
            #pragma unroll
            for (int ni=0;ni<4;ni++){
                int n = (wn*32 + ni*8 + gid)*20;
                bhf[ni][0] = sBh[n + ci];  bhf[ni][1] = sBh[n + ci + 4];
            }
            #pragma unroll
            for (int mi=0;mi<4;mi++){
                int m0 = (wm*64 + mi*16 + gid)*20;
                uint32_t ah[4] = {sAh[m0+ci], sAh[m0+160+ci], sAh[m0+ci+4], sAh[m0+160+ci+4]};
                #pragma unroll
                for (int ni=0;ni<4;ni++)
                    mma16816(acc[mi][ni], ah, bhf[ni]);
            }
        }
    }

    float* Cb  = WF32 ? C  + (size_t)blockIdx.z * sC : nullptr;
    fp16*  Chb = WH16 ? Ch + (size_t)blockIdx.z * sC : nullptr;
    #pragma unroll
    for (int mi=0;mi<4;mi++){
        int row = bm + wm*64 + mi*16 + gid;
        #pragma unroll
        for (int ni=0;ni<4;ni++){
            int col = bn + wn*32 + ni*8 + tig*2;
            float2 v0 = make_float2(acc[mi][ni][0], acc[mi][ni][1]);
            float2 v1 = make_float2(acc[mi][ni][2], acc[mi][ni][3]);
            if (bias){
                float2 bb = *(const float2*)(bias + col);
                v0.x += bb.x; v0.y += bb.y; v1.x += bb.x; v1.y += bb.y;
            }
            if (RELU){
                v0.x=fmaxf(v0.x,0.f); v0.y=fmaxf(v0.y,0.f);
                v1.x=fmaxf(v1.x,0.f); v1.y=fmaxf(v1.y,0.f);
            }
            if (WF32){
                *(float2*)(Cb + (size_t)row    *N + col) = v0;
                *(float2*)(Cb + (size_t)(row+8)*N + col) = v1;
            }
            if (WH16){
                *(uint32_t*)(Chb + (size_t)row    *N + col) = hquant(v0.x, v0.y);
                *(uint32_t*)(Chb + (size_t)(row+8)*N + col) = hquant(v1.x, v1.y);
            }
        }
    }
}

// ============================================================================
// Fused attention exp kernel, plain fp16:
// per (b,h,i0): logits = Q*K^T/8; E = exp; row sums -> sinv;
// store E (bf16) to P for causal tiles.
// ============================================================================
#define ATTN_SMEM (2*128*36*4)
__global__ __launch_bounds__(256) void attn_exp(
    const fp16* __restrict__ qk,
    bf16* __restrict__ P, float* __restrict__ sinv)
{
    extern __shared__ uint32_t smx[];
    uint32_t* sQh = smx;
    uint32_t* sKh = smx + 128*36;
    __shared__ float sred[128];

    const int bh = blockIdx.x;
    const int ti = blockIdx.y;
    const int i0 = ti * 128;
    const int b  = bh >> 3, h = bh & 7;
    const size_t qoff = (size_t)(b*Lq)*1024 + h*64;

    const int t = threadIdx.x;
    const int lane = t & 31, wid = t >> 5;
    const int wm = wid >> 2, wn = wid & 3;
    const int gid = lane >> 2, tig = lane & 3;
    const int fr = t >> 1, half = t & 1;

    if (t < 128) sred[t] = 0.f;

    // load Q tile [128 x 64]
    {
        const uint4* sh = (const uint4*)(qk + qoff + (size_t)(i0+fr)*1024 + half*32);
        uint4* dh = (uint4*)(sQh + fr*36 + half*16);
        dh[0]=sh[0]; dh[1]=sh[1]; dh[2]=sh[2]; dh[3]=sh[3];
    }

    float rsum[4][2];
    #pragma unroll
    for (int mi=0;mi<4;mi++){ rsum[mi][0]=0.f; rsum[mi][1]=0.f; }

    for (int jt = 0; jt < Lq/128; jt++){
        const int j0 = jt * 128;
        __syncthreads();
        {   // K tile [128 x 64]
            const uint4* sh = (const uint4*)(qk + qoff + 512 + (size_t)(j0+fr)*1024 + half*32);
            uint4* dh = (uint4*)(sKh + fr*36 + half*16);
            dh[0]=sh[0]; dh[1]=sh[1]; dh[2]=sh[2]; dh[3]=sh[3];
        }
        __syncthreads();

        float acc[4][4][4];
        #pragma unroll
        for (int i=0;i<4;i++)
            #pragma unroll
            for (int j=0;j<4;j++)
                #pragma unroll
                for (int q=0;q<4;q++) acc[i][j][q] = 0.f;

        #pragma unroll
        for (int ks=0; ks<4; ks++){
            const int ci = tig + ks*8;
            uint32_t bhf[4][2];
            #pragma unroll
            for (int ni=0;ni<4;ni++){
                int n = (wn*32 + ni*8 + gid)*36;
                bhf[ni][0] = sKh[n + ci];  bhf[ni][1] = sKh[n + ci + 4];
            }
            #pragma unroll
            for (int mi=0;mi<4;mi++){
                int m0 = (wm*64 + mi*16 + gid)*36;
                uint32_t ah[4] = {sQh[m0+ci], sQh[m0+288+ci], sQh[m0+ci+4], sQh[m0+288+ci+4]};
                #pragma unroll
                for (int ni=0;ni<4;ni++)
                    mma16816(acc[mi][ni], ah, bhf[ni]);
            }
        }

        const bool store = (jt <= ti);
        #pragma unroll
        for (int mi=0;mi<4;mi++){
            const int row = i0 + wm*64 + mi*16 + gid;
            #pragma unroll
            for (int ni=0;ni<4;ni++){
                float e0 = __expf(acc[mi][ni][0] * 0.125f);
                float e1 = __expf(acc[mi][ni][1] * 0.125f);
                float e2 = __expf(acc[mi][ni][2] * 0.125f);
                float e3 = __expf(acc[mi][ni][3] * 0.125f);
                rsum[mi][0] += e0 + e1;
                rsum[mi][1] += e2 + e3;
                if (store){
                    const int col = j0 + wn*32 + ni*8 + tig*2;
                    bf16* p0 = P + ((size_t)bh*Lq + row)*Lq + col;
                    *(uint32_t*)p0          = bpack(e0, e1);
                    *(uint32_t*)(p0 + 8*Lq) = bpack(e2, e3);
                }
            }
        }
    }

    #pragma unroll
    for (int mi=0;mi<4;mi++){
        float r0 = rsum[mi][0], r1 = rsum[mi][1];
        r0 += __shfl_xor_sync(0xffffffffu, r0, 1);
        r0 += __shfl_xor_sync(0xffffffffu, r0, 2);
        r1 += __shfl_xor_sync(0xffffffffu, r1, 1);
        r1 += __shfl_xor_sync(0xffffffffu, r1, 2);
        if (tig == 0){
            atomicAdd(&sred[wm*64 + mi*16 + gid    ], r0);
            atomicAdd(&sred[wm*64 + mi*16 + gid + 8], r1);
        }
    }
    __syncthreads();
    if (t < 128)
        sinv[(size_t)bh*Lq + i0 + t] = 0.125f / sred[t];
}

// ============================================================================
// A[b,i,j] = sum_h P[b,h,i,j] * sinv[b,h,i]   (causal tiles only; bf16 P)
// ============================================================================
__global__ __launch_bounds__(256) void attn_accum(
    const bf16* __restrict__ P, const float* __restrict__ sinv, float* __restrict__ A)
{
    const int tj = blockIdx.x, ti = blockIdx.y, b = blockIdx.z;
    if (tj > ti) return;
    const int i0 = ti*128, j0 = tj*128;
    __shared__ float ss[8][128];
    const int t = threadIdx.x;
    #pragma unroll
    for (int u=0;u<4;u++){
        int idx = t + u*256;
        int h = idx >> 7, r = idx & 127;
        ss[h][r] = sinv[((size_t)(b*Hq + h))*Lq + i0 + r];
    }
    __syncthreads();
    const size_t bs = (size_t)b*Hq*Lq*Lq;
    #pragma unroll
    for (int u=0;u<8;u++){
        int idx = t + u*256;
        int r = idx >> 4, c = (idx & 15)*8;
        float a[8];
        #pragma unroll
        for (int q=0;q<8;q++) a[q] = 0.f;
        #pragma unroll
        for (int h=0; h<8; h++){
            const uint4 pv = *(const uint4*)(P + bs + ((size_t)h*Lq + i0 + r)*Lq + j0 + c);
            const float s = ss[h][r];
            float2 f0 = __bfloat1622float2(*(const __nv_bfloat162*)&pv.x);
            float2 f1 = __bfloat1622float2(*(const __nv_bfloat162*)&pv.y);
            float2 f2 = __bfloat1622float2(*(const __nv_bfloat162*)&pv.z);
            float2 f3 = __bfloat1622float2(*(const __nv_bfloat162*)&pv.w);
            a[0]=fmaf(f0.x,s,a[0]); a[1]=fmaf(f0.y,s,a[1]);
            a[2]=fmaf(f1.x,s,a[2]); a[3]=fmaf(f1.y,s,a[3]);
            a[4]=fmaf(f2.x,s,a[4]); a[5]=fmaf(f2.y,s,a[5]);
            a[6]=fmaf(f3.x,s,a[6]); a[7]=fmaf(f3.y,s,a[7]);
        }
        float* dst = A + ((size_t)(b*Lq) + i0 + r)*Lq + j0 + c;
        *(float4*)dst     = make_float4(a[0],a[1],a[2],a[3]);
        *(float4*)(dst+4) = make_float4(a[4],a[5],a[6],a[7]);
    }
}

// ============================================================================
// W = softmax_j<=i ( A + exp(-(i-j)*0.1) ); writes fp16 W.
// ============================================================================
__global__ __launch_bounds__(256) void make_w(
    const float* __restrict__ A, fp16* __restrict__ Wh)
{
    const int row = blockIdx.x;
    const int i   = row & (Lq-1);
    const float* a = A + (size_t)row * Lq;
    const int t = threadIdx.x;
    const int j0 = t*4;
    float4 av = *(const float4*)(a + j0);
    float v[4]; float s = 0.f;
    const float arr[4] = {av.x, av.y, av.z, av.w};
    #pragma unroll
    for (int u=0;u<4;u++){
        int j = j0 + u;
        float val = 0.f;
        if (j <= i){
            float pos = __expf((float)(j - i) * 0.1f);
            val = __expf(arr[u] + pos);
        }
        v[u] = val; s += val;
    }
    s = warp_sum(s);
    __shared__ float red[8];
    if ((t & 31) == 0) red[t >> 5] = s;
    __syncthreads();
    float tot = 0.f;
    #pragma unroll
    for (int w=0;w<8;w++) tot += red[w];
    float inv = 1.f / tot;
    *(uint2*)(Wh + (size_t)row*Lq + j0) =
        make_uint2(hquant(v[0]*inv, v[1]*inv), hquant(v[2]*inv, v[3]*inv));
}

// ============================================================================
// Batched transpose + quantize: xt[b][e][l] = fp16(x[b][l][e])
// ============================================================================
__global__ __launch_bounds__(256) void transpose_x(
    const float* __restrict__ x, fp16* __restrict__ xt)
{
    __shared__ float tile[32][33];
    const int b  = blockIdx.z;
    const int l0 = blockIdx.y * 32, e0 = blockIdx.x * 32;
    const float* xp = x + (size_t)b * Lq * Eq;
    const int tx = threadIdx.x, ty = threadIdx.y;
    #pragma unroll
    for (int j=0;j<32;j+=8)
        tile[ty+j][tx] = xp[(size_t)(l0+ty+j)*Eq + e0 + tx];
    __syncthreads();
    const size_t base = (size_t)b * Eq * Lq;
    #pragma unroll
    for (int j=0;j<32;j+=8)
        xt[base + (size_t)(e0+ty+j)*Lq + l0 + tx] = __float2half_rn(tile[tx][ty+j]);
}

// ============================================================================
// LayerNorm kernels (one warp per 512-wide row); optional fp16 output
// ============================================================================
template<int WH>
__global__ __launch_bounds__(256) void add_ln2(
    const float* __restrict__ x, const float* __restrict__ y,
    const float* __restrict__ g1, const float* __restrict__ b1,
    const float* __restrict__ g2, const float* __restrict__ b2,
    float* __restrict__ out, fp16* __restrict__ oh)
{
    const int row  = blockIdx.x * 8 + (threadIdx.x >> 5);
    const int lane = threadIdx.x & 31;
    const float* xr = x + (size_t)row * Eq;
    const float* yr = y + (size_t)row * Eq;
    float v[16]; float s = 0.f;
    #pragma unroll
    for (int u=0;u<16;u++){ int c = lane + u*32; v[u] = xr[c] + yr[c]; s += v[u]; }
    s = warp_sum(s);
    float mean = s * (1.0f/Eq);
    float sq = 0.f;
    #pragma unroll
    for (int u=0;u<16;u++){ float d = v[u]-mean; sq += d*d; }
    sq = warp_sum(sq);
    float rstd = rsqrtf(sq*(1.0f/Eq) + 1e-5f);
    float s2 = 0.f;
    #pragma unroll
    for (int u=0;u<16;u++){ int c = lane + u*32; v[u] = (v[u]-mean)*rstd*g1[c] + b1[c]; s2 += v[u]; }
    s2 = warp_sum(s2);
    float m2 = s2 * (1.0f/Eq);
    float q2 = 0.f;
    #pragma unroll
    for (int u=0;u<16;u++){ float d = v[u]-m2; q2 += d*d; }
    q2 = warp_sum(q2);
    float r2 = rsqrtf(q2*(1.0f/Eq) + 1e-5f);
    float* orow = out + (size_t)row * Eq;
    #pragma unroll
    for (int u=0;u<16;u++){
        int c = lane + u*32;
        float o = (v[u]-m2)*r2*g2[c] + b2[c];
        orow[c] = o;
        if (WH) oh[(size_t)row*Eq + c] = __float2half_rn(o);
    }
}

template<int WH>
__global__ __launch_bounds__(256) void add_ln1(
    const float* __restrict__ x, const float* __restrict__ y,
    const float* __restrict__ g, const float* __restrict__ b,
    float* __restrict__ out, fp16* __restrict__ oh)
{
    const int row  = blockIdx.x * 8 + (threadIdx.x >> 5);
    const int lane = threadIdx.x & 31;
    const float* xr = x + (size_t)row * Eq;
    const float* yr = y + (size_t)row * Eq;
    float v[16]; float s = 0.f;
    #pragma unroll
    for (int u=0;u<16;u++){ int c = lane + u*32; v[u] = xr[c] + yr[c]; s += v[u]; }
    s = warp_sum(s);
    float mean = s * (1.0f/Eq);
    float sq = 0.f;
    #pragma unroll
    for (int u=0;u<16;u++){ float d = v[u]-mean; sq += d*d; }
    sq = warp_sum(sq);
    float rstd = rsqrtf(sq*(1.0f/Eq) + 1e-5f);
    float* orow = out + (size_t)row * Eq;
    #pragma unroll
    for (int u=0;u<16;u++){
        int c = lane + u*32;
        float o = (v[u]-mean)*rstd*g[c] + b[c];
        orow[c] = o;
        if (WH) oh[(size_t)row*Eq + c] = __float2half_rn(o);
    }
}

// ============================================================================
// Launch
// ============================================================================
extern "C" void kernel_launch(void* const* d_in, const int* in_sizes, int n_in,
                              void* d_out, int out_size)
{
    const float* input = (const float*)d_in[0];
    const float* Wqkv  = (const float*)d_in[1];
    const float* bqkv  = (const float*)d_in[2];
    const float* W1    = (const float*)d_in[3];
    const float* b1    = (const float*)d_in[4];
    const float* W2    = (const float*)d_in[5];
    const float* b2    = (const float*)d_in[6];
    const float* g1    = (const float*)d_in[7];
    const float* bt1   = (const float*)d_in[8];
    const float* g2    = (const float*)d_in[9];
    const float* bt2   = (const float*)d_in[10];
    const float* g3    = (const float*)d_in[11];
    const float* bt3   = (const float*)d_in[12];

    float *x, *sv, *A, *tb;
    bf16 *P;
    fp16 *xh,*qk,*aw,*xt,*hb,*Wq,*W1f,*W2f;
    cudaGetSymbolAddress((void**)&x,  g_x);
    cudaGetSymbolAddress((void**)&sv, g_sv);
    cudaGetSymbolAddress((void**)&A,  g_A);
    cudaGetSymbolAddress((void**)&tb, g_t);
    cudaGetSymbolAddress((void**)&P,  g_P);
    cudaGetSymbolAddress((void**)&xh, g_xh);
    cudaGetSymbolAddress((void**)&qk, g_qk);
    cudaGetSymbolAddress((void**)&aw, g_aw);
    cudaGetSymbolAddress((void**)&xt, g_xt);
    cudaGetSymbolAddress((void**)&hb, g_h);
    cudaGetSymbolAddress((void**)&Wq, g_Wq);
    cudaGetSymbolAddress((void**)&W1f,g_W1);
    cudaGetSymbolAddress((void**)&W2f,g_W2);

    cudaFuncSetAttribute(attn_exp, cudaFuncAttributeMaxDynamicSharedMemorySize, ATTN_SMEM);

    // one-time weight quantization + input copy/quant
    for (int d = 0; d < 4; d++){
        int n4 = 1024*512/4;
        quant_arr<<<(n4+255)/256, 256>>>(Wqkv + (size_t)d*1536*512,
                                         Wq + (size_t)d*1024*512, n4);
    }
    {
        int n4 = 4*2048*512/4;
        quant_arr<<<(n4+255)/256, 256>>>(W1, W1f, n4);
        quant_arr<<<(n4+255)/256, 256>>>(W2, W2f, n4);
    }
    {
        int n4 = Mq*Eq/4;
        quant_copy<<<(n4+255)/256, 256>>>(input, x, xh, n4);
    }

    for (int d = 0; d < 4; d++){
        const float* bq = bqkv + (size_t)d * 1536;

        // q|k projection -> fp16 qk (v/out-proj of Wqkv are dead in the reference)
        mma_gemm2<0,0,1><<<dim3(1024/128, Mq/128, 1), 256>>>(
            xh, Wq + (size_t)d*1024*512,
            bq, nullptr, qk, Mq, 1024, 512, 0, 0, 0, 0);

        // fused logits+exp (stores causal bf16 P, computes sinv)
        attn_exp<<<dim3(Bq*Hq, Lq/128), 256, ATTN_SMEM>>>(qk, P, sv);

        // head-averaged A over causal tiles (memory-bound)
        attn_accum<<<dim3(Lq/128, Lq/128, Bq), 256>>>(P, sv, A);

        // second softmax with causal mask + pos bias -> fp16 attention weights
        make_w<<<Bq*Lq, 256>>>(A, aw);

        // sa = W @ x: fp16 transpose of x, then NT GEMM w/ causal k cutoff
        transpose_x<<<dim3(Eq/32, Lq/32, Bq), dim3(32,8)>>>(x, xt);
        mma_gemm2<0,1,0><<<dim3(Eq/128, Lq/128, Bq), 256>>>(
            aw, xt, nullptr, tb, nullptr,
            Lq, Eq, Lq, (long)Lq*Lq, (long)Eq*Lq, (long)Lq*Eq, 1);

        // x = LN2(LN1(x + sa))  (cross-attn block is a double-LN no-op)
        add_ln2<1><<<Mq/8, 256>>>(x, tb,
                                  g1 + d*Eq, bt1 + d*Eq,
                                  g2 + d*Eq, bt2 + d*Eq, x, xh);

        // FFN1 -> fp16 h (relu), FFN2 -> fp32 tb
        mma_gemm2<1,0,1><<<dim3(FFq/128, Mq/128, 1), 256>>>(
            xh, W1f + (size_t)d*2048*512,
            b1 + (size_t)d*FFq, nullptr, hb, Mq, FFq, Eq, 0, 0, 0, 0);
        mma_gemm2<0,1,0><<<dim3(Eq/128, Mq/128, 1), 256>>>(
            hb, W2f + (size_t)d*512*2048,
            b2 + (size_t)d*Eq, tb, nullptr, Mq, Eq, FFq, 0, 0, 0, 0);

        if (d == 3)
            add_ln1<0><<<Mq/8, 256>>>(x, tb, g3 + d*Eq, bt3 + d*Eq,
                                      (float*)d_out, nullptr);
        else
            add_ln1<1><<<Mq/8, 256>>>(x, tb, g3 + d*Eq, bt3 + d*Eq, x, xh);
    }
}

// round 9
// speedup vs baseline: 2.3013x; 1.1677x over previous
#include <cuda_runtime.h>
#include <cuda_fp16.h>
#include <cuda_bf16.h>
#include <math.h>
#include <stdint.h>

// Problem constants
#define Bq   8
#define Lq   1024
#define Eq   512
#define Hq   8
#define FFq  2048
#define Mq   (Bq*Lq)          // 8192 tokens

typedef __half        fp16;
typedef __nv_bfloat16 bf16;

// ---------------- scratch (static device globals; allocation-free) ----------
__device__ float g_x [Mq*Eq];        // current activations (fp32, residual path)
__device__ float g_sv[Bq*Hq*Lq];     // per-(b,h,i) 0.125/sum(exp)
__device__ float g_t [Mq*Eq];        // sa / ff temp (fp32)
__device__ bf16  g_P [(size_t)Bq*Hq*Lq*Lq];  // per-head exp(logits), bf16, causal tiles

// fp16 buffers (plain quantized)
__device__ fp16 g_xh [Mq*Eq];
__device__ fp16 g_qk [Mq*1024];
__device__ fp16 g_aw [(size_t)Bq*Lq*Lq];
__device__ fp16 g_xt [Bq*Eq*Lq];
__device__ fp16 g_h  [Mq*FFq];
__device__ fp16 g_Wq [4*1024*512];
__device__ fp16 g_W1 [4*2048*512];
__device__ fp16 g_W2 [4*512*2048];

// ---------------- helpers ------------------------------------------------------
__device__ __forceinline__ float warp_sum(float s){
    #pragma unroll
    for (int o=16;o;o>>=1) s += __shfl_xor_sync(0xffffffffu, s, o);
    return s;
}
__device__ __forceinline__ uint32_t hquant(float x0, float x1){
    return (uint32_t)__half_as_ushort(__float2half_rn(x0)) |
           ((uint32_t)__half_as_ushort(__float2half_rn(x1)) << 16);
}
__device__ __forceinline__ uint32_t bpack(float x0, float x1){
    __nv_bfloat162 b = __floats2bfloat162_rn(x0, x1);
    return *(uint32_t*)&b;
}
__device__ __forceinline__ uint32_t smem_u32(const void* p){
    uint32_t a;
    asm("{ .reg .u64 t; cvta.to.shared.u64 t, %1; cvt.u32.u64 %0, t; }" : "=r"(a) : "l"(p));
    return a;
}
__device__ __forceinline__ void cp16(uint32_t dst, const void* src){
    asm volatile("cp.async.cg.shared.global [%0], [%1], 16;" :: "r"(dst), "l"(src));
}
#define CP_COMMIT() asm volatile("cp.async.commit_group;" ::: "memory")
#define CP_WAIT0()  asm volatile("cp.async.wait_group 0;" ::: "memory")
#define CP_WAIT1()  asm volatile("cp.async.wait_group 1;" ::: "memory")

__device__ __forceinline__ void mma16816(float* c, const uint32_t* a, const uint32_t* b){
    asm volatile(
        "mma.sync.aligned.m16n8k16.row.col.f32.f16.f16.f32 "
        "{%0,%1,%2,%3}, {%4,%5,%6,%7}, {%8,%9}, {%0,%1,%2,%3};\n"
        : "+f"(c[0]), "+f"(c[1]), "+f"(c[2]), "+f"(c[3])
        : "r"(a[0]), "r"(a[1]), "r"(a[2]), "r"(a[3]), "r"(b[0]), "r"(b[1]));
}

// ============================================================================
// Quantization kernels: fp32 -> fp16 (optionally keep fp32 copy)
// ============================================================================
__global__ __launch_bounds__(256) void quant_arr(
    const float* __restrict__ in, fp16* __restrict__ oh, int n4)
{
    int i = blockIdx.x*256 + threadIdx.x;
    if (i >= n4) return;
    float4 v = ((const float4*)in)[i];
    ((uint2*)oh)[i] = make_uint2(hquant(v.x, v.y), hquant(v.z, v.w));
}

__global__ __launch_bounds__(256) void quant_copy(
    const float* __restrict__ in, float* __restrict__ out,
    fp16* __restrict__ oh, int n4)
{
    int i = blockIdx.x*256 + threadIdx.x;
    if (i >= n4) return;
    float4 v = ((const float4*)in)[i];
    ((float4*)out)[i] = v;
    ((uint2*)oh)[i] = make_uint2(hquant(v.x, v.y), hquant(v.z, v.w));
}

// ============================================================================
// Tensor-core GEMM NT, fp16 x fp16, fp32 accumulate, cp.async 2-stage pipeline:
//   C[M,N] = A[M,K] * B[N,K]^T (+bias, relu), batched via z.
// Block tile 128x128, BK=32, 256 threads (2x4 warps, 64x32 each).
// ============================================================================
template<int RELU, int WF32, int WH16>
__global__ __launch_bounds__(256, 2) void mma_gemm2(
    const fp16* __restrict__ Ah, const fp16* __restrict__ Bh,
    const float* __restrict__ bias,
    float* __restrict__ C, fp16* __restrict__ Ch,
    int M, int N, int K, long sA, long sB, long sC, int causal)
{
    __shared__ uint32_t sAh[2*2560], sBh[2*2560];   // 2 stages x 128 rows x 20 u32
    const int bm = blockIdx.y * 128, bn = blockIdx.x * 128;
    const fp16* Abh = Ah + (size_t)blockIdx.z * sA;
    const fp16* Bbh = Bh + (size_t)blockIdx.z * sB;

    const int t    = threadIdx.x;
    const int lane = t & 31, wid = t >> 5;
    const int wm   = wid >> 2, wn = wid & 3;
    const int gid  = lane >> 2, tig = lane & 3;
    const int fr   = t >> 1, half = t & 1;

    float acc[4][4][4];
    #pragma unroll
    for (int i=0;i<4;i++)
        #pragma unroll
        for (int j=0;j<4;j++)
            #pragma unroll
            for (int q=0;q<4;q++) acc[i][j][q] = 0.f;

    const uint32_t da = smem_u32(sAh) + fr*80 + half*32;
    const uint32_t db = smem_u32(sBh) + fr*80 + half*32;
    const fp16* ga = Abh + (size_t)(bm+fr)*K + half*16;
    const fp16* gb = Bbh + (size_t)(bn+fr)*K + half*16;

    const int kend = causal ? (bm + 128) : K;
    const int nch  = kend >> 5;

    // prologue: stage 0
    {
        cp16(da,      ga);     cp16(da + 16, ga + 8);
        cp16(db,      gb);     cp16(db + 16, gb + 8);
        CP_COMMIT();
    }

    for (int ch = 0; ch < nch; ch++){
        if (ch + 1 < nch){
            const uint32_t st = ((ch+1) & 1) * 10240;
            const fp16* gA = ga + ((ch+1) << 5);
            const fp16* gB = gb + ((ch+1) << 5);
            cp16(da + st,      gA);     cp16(da + st + 16, gA + 8);
            cp16(db + st,      gB);     cp16(db + st + 16, gB + 8);
            CP_COMMIT();
            CP_WAIT1();
        } else {
            CP_WAIT0();
        }
        __syncthreads();

        const uint32_t* pA = sAh + (ch & 1) * 2560;
        const uint32_t* pB = sBh + (ch & 1) * 2560;
        #pragma unroll
        for (int ks=0; ks<2; ks++){
            const int ci = tig + ks*8;
            uint32_t bhf[4][2];
            #pragma unroll
            for (int ni=0;ni<4;ni++){
                int n = (wn*32 + ni*8 + gid)*20;
                bhf[ni][0] = pB[n + ci];  bhf[ni][1] = pB[n + ci + 4];
            }
            #pragma unroll
            for (int mi=0;mi<4;mi++){
                int m0 = (wm*64 + mi*16 + gid)*20;
                uint32_t ah[4] = {pA[m0+ci], pA[m0+160+ci], pA[m0+ci+4], pA[m0+160+ci+4]};
                #pragma unroll
                for (int ni=0;ni<4;ni++)
                    mma16816(acc[mi][ni], ah, bhf[ni]);
            }
        }
        __syncthreads();
    }

    float* Cb  = WF32 ? C  + (size_t)blockIdx.z * sC : nullptr;
    fp16*  Chb = WH16 ? Ch + (size_t)blockIdx.z * sC : nullptr;
    #pragma unroll
    for (int mi=0;mi<4;mi++){
        int row = bm + wm*64 + mi*16 + gid;
        #pragma unroll
        for (int ni=0;ni<4;ni++){
            int col = bn + wn*32 + ni*8 + tig*2;
            float2 v0 = make_float2(acc[mi][ni][0], acc[mi][ni][1]);
            float2 v1 = make_float2(acc[mi][ni][2], acc[mi][ni][3]);
            if (bias){
                float2 bb = *(const float2*)(bias + col);
                v0.x += bb.x; v0.y += bb.y; v1.x += bb.x; v1.y += bb.y;
            }
            if (RELU){
                v0.x=fmaxf(v0.x,0.f); v0.y=fmaxf(v0.y,0.f);
                v1.x=fmaxf(v1.x,0.f); v1.y=fmaxf(v1.y,0.f);
            }
            if (WF32){
                *(float2*)(Cb + (size_t)row    *N + col) = v0;
                *(float2*)(Cb + (size_t)(row+8)*N + col) = v1;
            }
            if (WH16){
                *(uint32_t*)(Chb + (size_t)row    *N + col) = hquant(v0.x, v0.y);
                *(uint32_t*)(Chb + (size_t)(row+8)*N + col) = hquant(v1.x, v1.y);
            }
        }
    }
}

// ============================================================================
// Fused attention exp kernel, fp16, cp.async-pipelined K tiles:
// per (b,h,i0): logits = Q*K^T/8; E = exp; row sums -> sinv;
// store E (bf16) to P for causal tiles.
// Dyn smem: sQ (128x36 u32) + 2 stages sK (128x36 u32 each) = 55296 B
// ============================================================================
#define ATTN_SMEM (3*128*36*4)
__global__ __launch_bounds__(256) void attn_exp(
    const fp16* __restrict__ qk,
    bf16* __restrict__ P, float* __restrict__ sinv)
{
    extern __shared__ uint32_t smx[];
    uint32_t* sQh = smx;
    uint32_t* sKh = smx + 128*36;            // two stages, 4608 u32 each
    __shared__ float sred[128];

    const int bh = blockIdx.x;
    const int ti = blockIdx.y;
    const int i0 = ti * 128;
    const int b  = bh >> 3, h = bh & 7;
    const size_t qoff = (size_t)(b*Lq)*1024 + h*64;

    const int t = threadIdx.x;
    const int lane = t & 31, wid = t >> 5;
    const int wm = wid >> 2, wn = wid & 3;
    const int gid = lane >> 2, tig = lane & 3;
    const int fr = t >> 1, half = t & 1;

    if (t < 128) sred[t] = 0.f;

    const uint32_t dk = smem_u32(sKh) + fr*144 + half*64;
    const fp16* gk = qk + qoff + 512 + (size_t)fr*1024 + half*32;

    // prologue: K stage 0
    {
        cp16(dk,      gk);       cp16(dk + 16, gk + 8);
        cp16(dk + 32, gk + 16);  cp16(dk + 48, gk + 24);
        CP_COMMIT();
    }

    // load Q tile [128 x 64] (plain)
    {
        const uint4* sh = (const uint4*)(qk + qoff + (size_t)(i0+fr)*1024 + half*32);
        uint4* dh = (uint4*)(sQh + fr*36 + half*16);
        dh[0]=sh[0]; dh[1]=sh[1]; dh[2]=sh[2]; dh[3]=sh[3];
    }

    float rsum[4][2];
    #pragma unroll
    for (int mi=0;mi<4;mi++){ rsum[mi][0]=0.f; rsum[mi][1]=0.f; }

    for (int jt = 0; jt < Lq/128; jt++){
        if (jt + 1 < Lq/128){
            const uint32_t st = ((jt+1) & 1) * 18432;
            const fp16* g = gk + (size_t)(jt+1)*128*1024;
            cp16(dk + st,      g);       cp16(dk + st + 16, g + 8);
            cp16(dk + st + 32, g + 16);  cp16(dk + st + 48, g + 24);
            CP_COMMIT();
            CP_WAIT1();
        } else {
            CP_WAIT0();
        }
        __syncthreads();

        const uint32_t* pK = sKh + (jt & 1) * 4608;
        float acc[4][4][4];
        #pragma unroll
        for (int i=0;i<4;i++)
            #pragma unroll
            for (int j=0;j<4;j++)
                #pragma unroll
                for (int q=0;q<4;q++) acc[i][j][q] = 0.f;

        #pragma unroll
        for (int ks=0; ks<4; ks++){
            const int ci = tig + ks*8;
            uint32_t bhf[4][2];
            #pragma unroll
            for (int ni=0;ni<4;ni++){
                int n = (wn*32 + ni*8 + gid)*36;
                bhf[ni][0] = pK[n + ci];  bhf[ni][1] = pK[n + ci + 4];
            }
            #pragma unroll
            for (int mi=0;mi<4;mi++){
                int m0 = (wm*64 + mi*16 + gid)*36;
                uint32_t ah[4] = {sQh[m0+ci], sQh[m0+288+ci], sQh[m0+ci+4], sQh[m0+288+ci+4]};
                #pragma unroll
                for (int ni=0;ni<4;ni++)
                    mma16816(acc[mi][ni], ah, bhf[ni]);
            }
        }
        __syncthreads();   // smem reads done before next stage overwrite

        const int j0 = jt * 128;
        const bool store = (jt <= ti);
        #pragma unroll
        for (int mi=0;mi<4;mi++){
            const int row = i0 + wm*64 + mi*16 + gid;
            #pragma unroll
            for (int ni=0;ni<4;ni++){
                float e0 = __expf(acc[mi][ni][0] * 0.125f);
                float e1 = __expf(acc[mi][ni][1] * 0.125f);
                float e2 = __expf(acc[mi][ni][2] * 0.125f);
                float e3 = __expf(acc[mi][ni][3] * 0.125f);
                rsum[mi][0] += e0 + e1;
                rsum[mi][1] += e2 + e3;
                if (store){
                    const int col = j0 + wn*32 + ni*8 + tig*2;
                    bf16* p0 = P + ((size_t)bh*Lq + row)*Lq + col;
                    *(uint32_t*)p0          = bpack(e0, e1);
                    *(uint32_t*)(p0 + 8*Lq) = bpack(e2, e3);
                }
            }
        }
    }

    #pragma unroll
    for (int mi=0;mi<4;mi++){
        float r0 = rsum[mi][0], r1 = rsum[mi][1];
        r0 += __shfl_xor_sync(0xffffffffu, r0, 1);
        r0 += __shfl_xor_sync(0xffffffffu, r0, 2);
        r1 += __shfl_xor_sync(0xffffffffu, r1, 1);
        r1 += __shfl_xor_sync(0xffffffffu, r1, 2);
        if (tig == 0){
            atomicAdd(&sred[wm*64 + mi*16 + gid    ], r0);
            atomicAdd(&sred[wm*64 + mi*16 + gid + 8], r1);
        }
    }
    __syncthreads();
    if (t < 128)
        sinv[(size_t)bh*Lq + i0 + t] = 0.125f / sred[t];
}

// ============================================================================
// Fused head-average + second softmax (A never materialized):
// per (b,i): a[j] = sum_h P[b,h,i,j]*sinv[b,h,i];
// W = softmax_{j<=i}( a + exp((j-i)*0.1) ); writes fp16 W.
// ============================================================================
__global__ __launch_bounds__(256) void make_w2(
    const bf16* __restrict__ P, const float* __restrict__ sinv,
    fp16* __restrict__ Wh)
{
    const int row = blockIdx.x;            // b*1024 + i
    const int b = row >> 10, i = row & 1023;
    const int t = threadIdx.x;
    __shared__ float sv8[8];
    if (t < 8) sv8[t] = sinv[(size_t)(b*8 + t)*Lq + i];
    __syncthreads();

    const int j0 = t*4;
    float v[4] = {0.f,0.f,0.f,0.f};
    float s = 0.f;
    if (j0 <= i){
        float a[4] = {0.f,0.f,0.f,0.f};
        const bf16* pb = P + ((size_t)(b*8)*Lq + i)*Lq + j0;
        #pragma unroll
        for (int h=0; h<8; h++){
            const uint2 pv = *(const uint2*)(pb + (size_t)h*Lq*Lq);
            const float sc = sv8[h];
            float2 f0 = __bfloat1622float2(*(const __nv_bfloat162*)&pv.x);
            float2 f1 = __bfloat1622float2(*(const __nv_bfloat162*)&pv.y);
            a[0] = fmaf(f0.x, sc, a[0]); a[1] = fmaf(f0.y, sc, a[1]);
            a[2] = fmaf(f1.x, sc, a[2]); a[3] = fmaf(f1.y, sc, a[3]);
        }
        #pragma unroll
        for (int u=0;u<4;u++){
            int j = j0 + u;
            if (j <= i){
                float pos = __expf((float)(j - i) * 0.1f);
                v[u] = __expf(a[u] + pos);
                s += v[u];
            }
        }
    }
    s = warp_sum(s);
    __shared__ float red[8];
    if ((t & 31) == 0) red[t >> 5] = s;
    __syncthreads();
    float tot = 0.f;
    #pragma unroll
    for (int w=0;w<8;w++) tot += red[w];
    float inv = 1.f / tot;
    *(uint2*)(Wh + (size_t)row*Lq + j0) =
        make_uint2(hquant(v[0]*inv, v[1]*inv), hquant(v[2]*inv, v[3]*inv));
}

// ============================================================================
// Batched transpose + quantize: xt[b][e][l] = fp16(x[b][l][e])
// ============================================================================
__global__ __launch_bounds__(256) void transpose_x(
    const float* __restrict__ x, fp16* __restrict__ xt)
{
    __shared__ float tile[32][33];
    const int b  = blockIdx.z;
    const int l0 = blockIdx.y * 32, e0 = blockIdx.x * 32;
    const float* xp = x + (size_t)b * Lq * Eq;
    const int tx = threadIdx.x, ty = threadIdx.y;
    #pragma unroll
    for (int j=0;j<32;j+=8)
        tile[ty+j][tx] = xp[(size_t)(l0+ty+j)*Eq + e0 + tx];
    __syncthreads();
    const size_t base = (size_t)b * Eq * Lq;
    #pragma unroll
    for (int j=0;j<32;j+=8)
        xt[base + (size_t)(e0+ty+j)*Lq + l0 + tx] = __float2half_rn(tile[tx][ty+j]);
}

// ============================================================================
// LayerNorm kernels (one warp per 512-wide row); optional fp16 output
// ============================================================================
template<int WH>
__global__ __launch_bounds__(256) void add_ln2(
    const float* __restrict__ x, const float* __restrict__ y,
    const float* __restrict__ g1, const float* __restrict__ b1,
    const float* __restrict__ g2, const float* __restrict__ b2,
    float* __restrict__ out, fp16* __restrict__ oh)
{
    const int row  = blockIdx.x * 8 + (threadIdx.x >> 5);
    const int lane = threadIdx.x & 31;
    const float* xr = x + (size_t)row * Eq;
    const float* yr = y + (size_t)row * Eq;
    float v[16]; float s = 0.f;
    #pragma unroll
    for (int u=0;u<16;u++){ int c = lane + u*32; v[u] = xr[c] + yr[c]; s += v[u]; }
    s = warp_sum(s);
    float mean = s * (1.0f/Eq);
    float sq = 0.f;
    #pragma unroll
    for (int u=0;u<16;u++){ float d = v[u]-mean; sq += d*d; }
    sq = warp_sum(sq);
    float rstd = rsqrtf(sq*(1.0f/Eq) + 1e-5f);
    float s2 = 0.f;
    #pragma unroll
    for (int u=0;u<16;u++){ int c = lane + u*32; v[u] = (v[u]-mean)*rstd*g1[c] + b1[c]; s2 += v[u]; }
    s2 = warp_sum(s2);
    float m2 = s2 * (1.0f/Eq);
    float q2 = 0.f;
    #pragma unroll
    for (int u=0;u<16;u++){ float d = v[u]-m2; q2 += d*d; }
    q2 = warp_sum(q2);
    float r2 = rsqrtf(q2*(1.0f/Eq) + 1e-5f);
    float* orow = out + (size_t)row * Eq;
    #pragma unroll
    for (int u=0;u<16;u++){
        int c = lane + u*32;
        float o = (v[u]-m2)*r2*g2[c] + b2[c];
        orow[c] = o;
        if (WH) oh[(size_t)row*Eq + c] = __float2half_rn(o);
    }
}

template<int WH>
__global__ __launch_bounds__(256) void add_ln1(
    const float* __restrict__ x, const float* __restrict__ y,
    const float* __restrict__ g, const float* __restrict__ b,
    float* __restrict__ out, fp16* __restrict__ oh)
{
    const int row  = blockIdx.x * 8 + (threadIdx.x >> 5);
    const int lane = threadIdx.x & 31;
    const float* xr = x + (size_t)row * Eq;
    const float* yr = y + (size_t)row * Eq;
    float v[16]; float s = 0.f;
    #pragma unroll
    for (int u=0;u<16;u++){ int c = lane + u*32; v[u] = xr[c] + yr[c]; s += v[u]; }
    s = warp_sum(s);
    float mean = s * (1.0f/Eq);
    float sq = 0.f;
    #pragma unroll
    for (int u=0;u<16;u++){ float d = v[u]-mean; sq += d*d; }
    sq = warp_sum(sq);
    float rstd = rsqrtf(sq*(1.0f/Eq) + 1e-5f);
    float* orow = out + (size_t)row * Eq;
    #pragma unroll
    for (int u=0;u<16;u++){
        int c = lane + u*32;
        float o = (v[u]-mean)*rstd*g[c] + b[c];
        orow[c] = o;
        if (WH) oh[(size_t)row*Eq + c] = __float2half_rn(o);
    }
}

// ============================================================================
// Launch
// ============================================================================
extern "C" void kernel_launch(void* const* d_in, const int* in_sizes, int n_in,
                              void* d_out, int out_size)
{
    const float* input = (const float*)d_in[0];
    const float* Wqkv  = (const float*)d_in[1];
    const float* bqkv  = (const float*)d_in[2];
    const float* W1    = (const float*)d_in[3];
    const float* b1    = (const float*)d_in[4];
    const float* W2    = (const float*)d_in[5];
    const float* b2    = (const float*)d_in[6];
    const float* g1    = (const float*)d_in[7];
    const float* bt1   = (const float*)d_in[8];
    const float* g2    = (const float*)d_in[9];
    const float* bt2   = (const float*)d_in[10];
    const float* g3    = (const float*)d_in[11];
    const float* bt3   = (const float*)d_in[12];

    float *x, *sv, *tb;
    bf16 *P;
    fp16 *xh,*qk,*aw,*xt,*hb,*Wq,*W1f,*W2f;
    cudaGetSymbolAddress((void**)&x,  g_x);
    cudaGetSymbolAddress((void**)&sv, g_sv);
    cudaGetSymbolAddress((void**)&tb, g_t);
    cudaGetSymbolAddress((void**)&P,  g_P);
    cudaGetSymbolAddress((void**)&xh, g_xh);
    cudaGetSymbolAddress((void**)&qk, g_qk);
    cudaGetSymbolAddress((void**)&aw, g_aw);
    cudaGetSymbolAddress((void**)&xt, g_xt);
    cudaGetSymbolAddress((void**)&hb, g_h);
    cudaGetSymbolAddress((void**)&Wq, g_Wq);
    cudaGetSymbolAddress((void**)&W1f,g_W1);
    cudaGetSymbolAddress((void**)&W2f,g_W2);

    cudaFuncSetAttribute(attn_exp, cudaFuncAttributeMaxDynamicSharedMemorySize, ATTN_SMEM);

    // one-time weight quantization + input copy/quant
    for (int d = 0; d < 4; d++){
        int n4 = 1024*512/4;
        quant_arr<<<(n4+255)/256, 256>>>(Wqkv + (size_t)d*1536*512,
                                         Wq + (size_t)d*1024*512, n4);
    }
    {
        int n4 = 4*2048*512/4;
        quant_arr<<<(n4+255)/256, 256>>>(W1, W1f, n4);
        quant_arr<<<(n4+255)/256, 256>>>(W2, W2f, n4);
    }
    {
        int n4 = Mq*Eq/4;
        quant_copy<<<(n4+255)/256, 256>>>(input, x, xh, n4);
    }

    for (int d = 0; d < 4; d++){
        const float* bq = bqkv + (size_t)d * 1536;

        // q|k projection -> fp16 qk (v/out-proj of Wqkv are dead in the reference)
        mma_gemm2<0,0,1><<<dim3(1024/128, Mq/128, 1), 256>>>(
            xh, Wq + (size_t)d*1024*512,
            bq, nullptr, qk, Mq, 1024, 512, 0, 0, 0, 0);

        // fused logits+exp (stores causal bf16 P, computes sinv)
        attn_exp<<<dim3(Bq*Hq, Lq/128), 256, ATTN_SMEM>>>(qk, P, sv);

        // fused head-average + second softmax -> fp16 attention weights
        make_w2<<<Bq*Lq, 256>>>(P, sv, aw);

        // sa = W @ x: fp16 transpose of x, then NT GEMM w/ causal k cutoff
        transpose_x<<<dim3(Eq/32, Lq/32, Bq), dim3(32,8)>>>(x, xt);
        mma_gemm2<0,1,0><<<dim3(Eq/128, Lq/128, Bq), 256>>>(
            aw, xt, nullptr, tb, nullptr,
            Lq, Eq, Lq, (long)Lq*Lq, (long)Eq*Lq, (long)Lq*Eq, 1);

        // x = LN2(LN1(x + sa))  (cross-attn block is a double-LN no-op)
        add_ln2<1><<<Mq/8, 256>>>(x, tb,
                                  g1 + d*Eq, bt1 + d*Eq,
                                  g2 + d*Eq, bt2 + d*Eq, x, xh);

        // FFN1 -> fp16 h (relu), FFN2 -> fp32 tb
        mma_gemm2<1,0,1><<<dim3(FFq/128, Mq/128, 1), 256>>>(
            xh, W1f + (size_t)d*2048*512,
            b1 + (size_t)d*FFq, nullptr, hb, Mq, FFq, Eq, 0, 0, 0, 0);
        mma_gemm2<0,1,0><<<dim3(Eq/128, Mq/128, 1), 256>>>(
            hb, W2f + (size_t)d*512*2048,
            b2 + (size_t)d*Eq, tb, nullptr, Mq, Eq, FFq, 0, 0, 0, 0);

        if (d == 3)
            add_ln1<0><<<Mq/8, 256>>>(x, tb, g3 + d*Eq, bt3 + d*Eq,
                                      (float*)d_out, nullptr);
        else
            add_ln1<1><<<Mq/8, 256>>>(x, tb, g3 + d*Eq, bt3 + d*Eq, x, xh);
    }
}

// round 10
// speedup vs baseline: 2.3080x; 1.0029x over previous
#include <cuda_runtime.h>
#include <cuda_fp16.h>
#include <cuda_bf16.h>
#include <math.h>
#include <stdint.h>

// Problem constants
#define Bq   8
#define Lq   1024
#define Eq   512
#define Hq   8
#define FFq  2048
#define Mq   (Bq*Lq)          // 8192 tokens

typedef __half        fp16;
typedef __nv_bfloat16 bf16;

// ---------------- scratch (static device globals; allocation-free) ----------
__device__ float g_x [Mq*Eq];        // current activations (fp32, residual path)
__device__ float g_sv[Bq*Hq*Lq];     // per-(b,h,i) 0.125/sum(exp)
__device__ float g_t [Mq*Eq];        // sa / ff temp (fp32)
__device__ bf16  g_P [(size_t)Bq*Hq*Lq*Lq];  // per-head exp(logits), bf16, causal tiles

// fp16 buffers (plain quantized)
__device__ fp16 g_xh [Mq*Eq];
__device__ fp16 g_qk [Mq*1024];
__device__ fp16 g_aw [(size_t)Bq*Lq*Lq];
__device__ fp16 g_xt [Bq*Eq*Lq];
__device__ fp16 g_h  [Mq*FFq];
__device__ fp16 g_Wq [4*1024*512];
__device__ fp16 g_W1 [4*2048*512];
__device__ fp16 g_W2 [4*512*2048];

// ---------------- helpers ------------------------------------------------------
__device__ __forceinline__ float warp_sum(float s){
    #pragma unroll
    for (int o=16;o;o>>=1) s += __shfl_xor_sync(0xffffffffu, s, o);
    return s;
}
__device__ __forceinline__ uint32_t hquant(float x0, float x1){
    return (uint32_t)__half_as_ushort(__float2half_rn(x0)) |
           ((uint32_t)__half_as_ushort(__float2half_rn(x1)) << 16);
}
__device__ __forceinline__ uint32_t bpack(float x0, float x1){
    __nv_bfloat162 b = __floats2bfloat162_rn(x0, x1);
    return *(uint32_t*)&b;
}
__device__ __forceinline__ uint32_t smem_u32(const void* p){
    uint32_t a;
    asm("{ .reg .u64 t; cvta.to.shared.u64 t, %1; cvt.u32.u64 %0, t; }" : "=r"(a) : "l"(p));
    return a;
}
__device__ __forceinline__ void cp16(uint32_t dst, const void* src){
    asm volatile("cp.async.cg.shared.global [%0], [%1], 16;" :: "r"(dst), "l"(src));
}
#define CP_COMMIT() asm volatile("cp.async.commit_group;" ::: "memory")
#define CP_WAIT0()  asm volatile("cp.async.wait_group 0;" ::: "memory")
#define CP_WAIT1()  asm volatile("cp.async.wait_group 1;" ::: "memory")

__device__ __forceinline__ void mma16816(float* c, const uint32_t* a, const uint32_t* b){
    asm volatile(
        "mma.sync.aligned.m16n8k16.row.col.f32.f16.f16.f32 "
        "{%0,%1,%2,%3}, {%4,%5,%6,%7}, {%8,%9}, {%0,%1,%2,%3};\n"
        : "+f"(c[0]), "+f"(c[1]), "+f"(c[2]), "+f"(c[3])
        : "r"(a[0]), "r"(a[1]), "r"(a[2]), "r"(a[3]), "r"(b[0]), "r"(b[1]));
}

// ============================================================================
// Quantization kernels: fp32 -> fp16 (optionally keep fp32 copy)
// ============================================================================
__global__ __launch_bounds__(256) void quant_arr(
    const float* __restrict__ in, fp16* __restrict__ oh, int n4)
{
    int i = blockIdx.x*256 + threadIdx.x;
    if (i >= n4) return;
    float4 v = ((const float4*)in)[i];
    ((uint2*)oh)[i] = make_uint2(hquant(v.x, v.y), hquant(v.z, v.w));
}

__global__ __launch_bounds__(256) void quant_copy(
    const float* __restrict__ in, float* __restrict__ out,
    fp16* __restrict__ oh, int n4)
{
    int i = blockIdx.x*256 + threadIdx.x;
    if (i >= n4) return;
    float4 v = ((const float4*)in)[i];
    ((float4*)out)[i] = v;
    ((uint2*)oh)[i] = make_uint2(hquant(v.x, v.y), hquant(v.z, v.w));
}

// ============================================================================
// Tensor-core GEMM NT, fp16 x fp16, fp32 accumulate.
// Tile 128(M) x 256(N), BK=32, 256 threads (2x4 warps, 64x64 each),
// 3-stage cp.async ring, single __syncthreads per chunk.
//   C[M,N] = A[M,K] * B[N,K]^T (+bias, relu), batched via z.
// ============================================================================
#define SA_U32   2560                   // A stage: 128 rows * 20 u32
#define SB_U32   5120                   // B stage: 256 rows * 20 u32
#define STG_U32  (SA_U32 + SB_U32)      // 7680
#define GEMM_SMEM (3 * STG_U32 * 4)     // 92160 B

template<int RELU, int WF32, int WH16>
__global__ __launch_bounds__(256, 1) void mma_gemm2(
    const fp16* __restrict__ Ah, const fp16* __restrict__ Bh,
    const float* __restrict__ bias,
    float* __restrict__ C, fp16* __restrict__ Ch,
    int M, int N, int K, long sA, long sB, long sC, int causal)
{
    extern __shared__ uint32_t sg[];
    const int bm = blockIdx.y * 128, bn = blockIdx.x * 256;
    const fp16* Abh = Ah + (size_t)blockIdx.z * sA;
    const fp16* Bbh = Bh + (size_t)blockIdx.z * sB;

    const int t    = threadIdx.x;
    const int lane = t & 31, wid = t >> 5;
    const int wm   = wid >> 2, wn = wid & 3;
    const int gid  = lane >> 2, tig = lane & 3;
    const int fr   = t >> 1, half = t & 1;

    float acc[4][8][4];
    #pragma unroll
    for (int i=0;i<4;i++)
        #pragma unroll
        for (int j=0;j<8;j++)
            #pragma unroll
            for (int q=0;q<4;q++) acc[i][j][q] = 0.f;

    const uint32_t sbase = smem_u32(sg);
    const uint32_t da  = sbase + (fr*20 + half*8)*4;
    const uint32_t db0 = sbase + (SA_U32 + fr*20 + half*8)*4;
    const uint32_t db1 = db0 + 128*20*4;
    const fp16* ga  = Abh + (size_t)(bm+fr)*K + half*16;
    const fp16* gb0 = Bbh + (size_t)(bn+fr)*K + half*16;
    const fp16* gb1 = Bbh + (size_t)(bn+128+fr)*K + half*16;

    const int kend = causal ? (bm + 128) : K;
    const int nch  = kend >> 5;

    #define G_ISSUE(ch_) do{ \
        const uint32_t st_ = (uint32_t)((ch_) % 3) * (STG_U32*4); \
        const fp16* A0_ = ga  + ((ch_) << 5); \
        const fp16* B0_ = gb0 + ((ch_) << 5); \
        const fp16* B1_ = gb1 + ((ch_) << 5); \
        cp16(da  + st_, A0_);  cp16(da  + st_ + 16, A0_ + 8); \
        cp16(db0 + st_, B0_);  cp16(db0 + st_ + 16, B0_ + 8); \
        cp16(db1 + st_, B1_);  cp16(db1 + st_ + 16, B1_ + 8); \
        CP_COMMIT(); }while(0)

    if (nch > 0) G_ISSUE(0);
    if (nch > 1) G_ISSUE(1);

    for (int ch = 0; ch < nch; ch++){
        if (ch + 1 < nch) CP_WAIT1(); else CP_WAIT0();
        __syncthreads();                 // stage ch visible; prior compute done
        if (ch + 2 < nch) G_ISSUE(ch+2); // safe: overwrites stage read 2 iters ago

        const uint32_t* pA = sg + (ch % 3) * STG_U32;
        const uint32_t* pB = pA + SA_U32;
        #pragma unroll
        for (int ks=0; ks<2; ks++){
            const int ci = tig + ks*8;
            uint32_t bhf[8][2];
            #pragma unroll
            for (int ni=0;ni<8;ni++){
                int n = (wn*64 + ni*8 + gid)*20;
                bhf[ni][0] = pB[n + ci];  bhf[ni][1] = pB[n + ci + 4];
            }
            #pragma unroll
            for (int mi=0;mi<4;mi++){
                int m0 = (wm*64 + mi*16 + gid)*20;
                uint32_t ah[4] = {pA[m0+ci], pA[m0+160+ci], pA[m0+ci+4], pA[m0+160+ci+4]};
                #pragma unroll
                for (int ni=0;ni<8;ni++)
                    mma16816(acc[mi][ni], ah, bhf[ni]);
            }
        }
    }
    #undef G_ISSUE

    float* Cb  = WF32 ? C  + (size_t)blockIdx.z * sC : nullptr;
    fp16*  Chb = WH16 ? Ch + (size_t)blockIdx.z * sC : nullptr;
    #pragma unroll
    for (int mi=0;mi<4;mi++){
        int row = bm + wm*64 + mi*16 + gid;
        #pragma unroll
        for (int ni=0;ni<8;ni++){
            int col = bn + wn*64 + ni*8 + tig*2;
            float2 v0 = make_float2(acc[mi][ni][0], acc[mi][ni][1]);
            float2 v1 = make_float2(acc[mi][ni][2], acc[mi][ni][3]);
            if (bias){
                float2 bb = *(const float2*)(bias + col);
                v0.x += bb.x; v0.y += bb.y; v1.x += bb.x; v1.y += bb.y;
            }
            if (RELU){
                v0.x=fmaxf(v0.x,0.f); v0.y=fmaxf(v0.y,0.f);
                v1.x=fmaxf(v1.x,0.f); v1.y=fmaxf(v1.y,0.f);
            }
            if (WF32){
                *(float2*)(Cb + (size_t)row    *N + col) = v0;
                *(float2*)(Cb + (size_t)(row+8)*N + col) = v1;
            }
            if (WH16){
                *(uint32_t*)(Chb + (size_t)row    *N + col) = hquant(v0.x, v0.y);
                *(uint32_t*)(Chb + (size_t)(row+8)*N + col) = hquant(v1.x, v1.y);
            }
        }
    }
}

// ============================================================================
// Fused attention exp kernel, fp16, 3-stage cp.async K ring:
// per (b,h,i0): logits = Q*K^T/8; E = exp; row sums -> sinv;
// store E (bf16) to P for causal tiles.
// Dyn smem: sQ (4608 u32) + 3 K stages (4608 u32 each) = 73728 B
// ============================================================================
#define ATTN_SMEM (4*4608*4)
__global__ __launch_bounds__(256) void attn_exp(
    const fp16* __restrict__ qk,
    bf16* __restrict__ P, float* __restrict__ sinv)
{
    extern __shared__ uint32_t smx[];
    uint32_t* sQh = smx;
    uint32_t* sK  = smx + 4608;
    __shared__ float sred[128];

    const int bh = blockIdx.x;
    const int ti = blockIdx.y;
    const int i0 = ti * 128;
    const int b  = bh >> 3, h = bh & 7;
    const size_t qoff = (size_t)(b*Lq)*1024 + h*64;

    const int t = threadIdx.x;
    const int lane = t & 31, wid = t >> 5;
    const int wm = wid >> 2, wn = wid & 3;
    const int gid = lane >> 2, tig = lane & 3;
    const int fr = t >> 1, half = t & 1;

    if (t < 128) sred[t] = 0.f;

    const uint32_t dk = smem_u32(sK) + fr*144 + half*64;
    const fp16* gk = qk + qoff + 512 + (size_t)fr*1024 + half*32;

    #define K_ISSUE(jt_) do{ \
        const uint32_t st_ = (uint32_t)((jt_) % 3) * 18432; \
        const fp16* g_ = gk + (size_t)(jt_)*128*1024; \
        cp16(dk + st_,      g_);       cp16(dk + st_ + 16, g_ + 8); \
        cp16(dk + st_ + 32, g_ + 16);  cp16(dk + st_ + 48, g_ + 24); \
        CP_COMMIT(); }while(0)

    K_ISSUE(0);
    K_ISSUE(1);

    // load Q tile [128 x 64]
    {
        const uint4* sh = (const uint4*)(qk + qoff + (size_t)(i0+fr)*1024 + half*32);
        uint4* dh = (uint4*)(sQh + fr*36 + half*16);
        dh[0]=sh[0]; dh[1]=sh[1]; dh[2]=sh[2]; dh[3]=sh[3];
    }

    float rsum[4][2];
    #pragma unroll
    for (int mi=0;mi<4;mi++){ rsum[mi][0]=0.f; rsum[mi][1]=0.f; }

    for (int jt = 0; jt < Lq/128; jt++){
        if (jt + 1 < Lq/128) CP_WAIT1(); else CP_WAIT0();
        __syncthreads();
        if (jt + 2 < Lq/128) K_ISSUE(jt+2);

        const uint32_t* pK = sK + (jt % 3) * 4608;
        float acc[4][4][4];
        #pragma unroll
        for (int i=0;i<4;i++)
            #pragma unroll
            for (int j=0;j<4;j++)
                #pragma unroll
                for (int q=0;q<4;q++) acc[i][j][q] = 0.f;

        #pragma unroll
        for (int ks=0; ks<4; ks++){
            const int ci = tig + ks*8;
            uint32_t bhf[4][2];
            #pragma unroll
            for (int ni=0;ni<4;ni++){
                int n = (wn*32 + ni*8 + gid)*36;
                bhf[ni][0] = pK[n + ci];  bhf[ni][1] = pK[n + ci + 4];
            }
            #pragma unroll
            for (int mi=0;mi<4;mi++){
                int m0 = (wm*64 + mi*16 + gid)*36;
                uint32_t ah[4] = {sQh[m0+ci], sQh[m0+288+ci], sQh[m0+ci+4], sQh[m0+288+ci+4]};
                #pragma unroll
                for (int ni=0;ni<4;ni++)
                    mma16816(acc[mi][ni], ah, bhf[ni]);
            }
        }

        const int j0 = jt * 128;
        const bool store = (jt <= ti);
        #pragma unroll
        for (int mi=0;mi<4;mi++){
            const int row = i0 + wm*64 + mi*16 + gid;
            #pragma unroll
            for (int ni=0;ni<4;ni++){
                float e0 = __expf(acc[mi][ni][0] * 0.125f);
                float e1 = __expf(acc[mi][ni][1] * 0.125f);
                float e2 = __expf(acc[mi][ni][2] * 0.125f);
                float e3 = __expf(acc[mi][ni][3] * 0.125f);
                rsum[mi][0] += e0 + e1;
                rsum[mi][1] += e2 + e3;
                if (store){
                    const int col = j0 + wn*32 + ni*8 + tig*2;
                    bf16* p0 = P + ((size_t)bh*Lq + row)*Lq + col;
                    *(uint32_t*)p0          = bpack(e0, e1);
                    *(uint32_t*)(p0 + 8*Lq) = bpack(e2, e3);
                }
            }
        }
    }
    #undef K_ISSUE

    #pragma unroll
    for (int mi=0;mi<4;mi++){
        float r0 = rsum[mi][0], r1 = rsum[mi][1];
        r0 += __shfl_xor_sync(0xffffffffu, r0, 1);
        r0 += __shfl_xor_sync(0xffffffffu, r0, 2);
        r1 += __shfl_xor_sync(0xffffffffu, r1, 1);
        r1 += __shfl_xor_sync(0xffffffffu, r1, 2);
        if (tig == 0){
            atomicAdd(&sred[wm*64 + mi*16 + gid    ], r0);
            atomicAdd(&sred[wm*64 + mi*16 + gid + 8], r1);
        }
    }
    __syncthreads();
    if (t < 128)
        sinv[(size_t)bh*Lq + i0 + t] = 0.125f / sred[t];
}

// ============================================================================
// Fused head-average + second softmax (A never materialized):
// per (b,i): a[j] = sum_h P[b,h,i,j]*sinv[b,h,i];
// W = softmax_{j<=i}( a + exp((j-i)*0.1) ); writes fp16 W.
// ============================================================================
__global__ __launch_bounds__(256) void make_w2(
    const bf16* __restrict__ P, const float* __restrict__ sinv,
    fp16* __restrict__ Wh)
{
    const int row = blockIdx.x;            // b*1024 + i
    const int b = row >> 10, i = row & 1023;
    const int t = threadIdx.x;
    __shared__ float sv8[8];
    if (t < 8) sv8[t] = sinv[(size_t)(b*8 + t)*Lq + i];
    __syncthreads();

    const int j0 = t*4;
    float v[4] = {0.f,0.f,0.f,0.f};
    float s = 0.f;
    if (j0 <= i){
        float a[4] = {0.f,0.f,0.f,0.f};
        const bf16* pb = P + ((size_t)(b*8)*Lq + i)*Lq + j0;
        #pragma unroll
        for (int h=0; h<8; h++){
            const uint2 pv = *(const uint2*)(pb + (size_t)h*Lq*Lq);
            const float sc = sv8[h];
            float2 f0 = __bfloat1622float2(*(const __nv_bfloat162*)&pv.x);
            float2 f1 = __bfloat1622float2(*(const __nv_bfloat162*)&pv.y);
            a[0] = fmaf(f0.x, sc, a[0]); a[1] = fmaf(f0.y, sc, a[1]);
            a[2] = fmaf(f1.x, sc, a[2]); a[3] = fmaf(f1.y, sc, a[3]);
        }
        #pragma unroll
        for (int u=0;u<4;u++){
            int j = j0 + u;
            if (j <= i){
                float pos = __expf((float)(j - i) * 0.1f);
                v[u] = __expf(a[u] + pos);
                s += v[u];
            }
        }
    }
    s = warp_sum(s);
    __shared__ float red[8];
    if ((t & 31) == 0) red[t >> 5] = s;
    __syncthreads();
    float tot = 0.f;
    #pragma unroll
    for (int w=0;w<8;w++) tot += red[w];
    float inv = 1.f / tot;
    *(uint2*)(Wh + (size_t)row*Lq + j0) =
        make_uint2(hquant(v[0]*inv, v[1]*inv), hquant(v[2]*inv, v[3]*inv));
}

// ============================================================================
// Batched transpose + quantize: xt[b][e][l] = fp16(x[b][l][e])
// ============================================================================
__global__ __launch_bounds__(256) void transpose_x(
    const float* __restrict__ x, fp16* __restrict__ xt)
{
    __shared__ float tile[32][33];
    const int b  = blockIdx.z;
    const int l0 = blockIdx.y * 32, e0 = blockIdx.x * 32;
    const float* xp = x + (size_t)b * Lq * Eq;
    const int tx = threadIdx.x, ty = threadIdx.y;
    #pragma unroll
    for (int j=0;j<32;j+=8)
        tile[ty+j][tx] = xp[(size_t)(l0+ty+j)*Eq + e0 + tx];
    __syncthreads();
    const size_t base = (size_t)b * Eq * Lq;
    #pragma unroll
    for (int j=0;j<32;j+=8)
        xt[base + (size_t)(e0+ty+j)*Lq + l0 + tx] = __float2half_rn(tile[tx][ty+j]);
}

// ============================================================================
// LayerNorm kernels (one warp per 512-wide row); optional fp16 output
// ============================================================================
template<int WH>
__global__ __launch_bounds__(256) void add_ln2(
    const float* __restrict__ x, const float* __restrict__ y,
    const float* __restrict__ g1, const float* __restrict__ b1,
    const float* __restrict__ g2, const float* __restrict__ b2,
    float* __restrict__ out, fp16* __restrict__ oh)
{
    const int row  = blockIdx.x * 8 + (threadIdx.x >> 5);
    const int lane = threadIdx.x & 31;
    const float* xr = x + (size_t)row * Eq;
    const float* yr = y + (size_t)row * Eq;
    float v[16]; float s = 0.f;
    #pragma unroll
    for (int u=0;u<16;u++){ int c = lane + u*32; v[u] = xr[c] + yr[c]; s += v[u]; }
    s = warp_sum(s);
    float mean = s * (1.0f/Eq);
    float sq = 0.f;
    #pragma unroll
    for (int u=0;u<16;u++){ float d = v[u]-mean; sq += d*d; }
    sq = warp_sum(sq);
    float rstd = rsqrtf(sq*(1.0f/Eq) + 1e-5f);
    float s2 = 0.f;
    #pragma unroll
    for (int u=0;u<16;u++){ int c = lane + u*32; v[u] = (v[u]-mean)*rstd*g1[c] + b1[c]; s2 += v[u]; }
    s2 = warp_sum(s2);
    float m2 = s2 * (1.0f/Eq);
    float q2 = 0.f;
    #pragma unroll
    for (int u=0;u<16;u++){ float d = v[u]-m2; q2 += d*d; }
    q2 = warp_sum(q2);
    float r2 = rsqrtf(q2*(1.0f/Eq) + 1e-5f);
    float* orow = out + (size_t)row * Eq;
    #pragma unroll
    for (int u=0;u<16;u++){
        int c = lane + u*32;
        float o = (v[u]-m2)*r2*g2[c] + b2[c];
        orow[c] = o;
        if (WH) oh[(size_t)row*Eq + c] = __float2half_rn(o);
    }
}

template<int WH>
__global__ __launch_bounds__(256) void add_ln1(
    const float* __restrict__ x, const float* __restrict__ y,
    const float* __restrict__ g, const float* __restrict__ b,
    float* __restrict__ out, fp16* __restrict__ oh)
{
    const int row  = blockIdx.x * 8 + (threadIdx.x >> 5);
    const int lane = threadIdx.x & 31;
    const float* xr = x + (size_t)row * Eq;
    const float* yr = y + (size_t)row * Eq;
    float v[16]; float s = 0.f;
    #pragma unroll
    for (int u=0;u<16;u++){ int c = lane + u*32; v[u] = xr[c] + yr[c]; s += v[u]; }
    s = warp_sum(s);
    float mean = s * (1.0f/Eq);
    float sq = 0.f;
    #pragma unroll
    for (int u=0;u<16;u++){ float d = v[u]-mean; sq += d*d; }
    sq = warp_sum(sq);
    float rstd = rsqrtf(sq*(1.0f/Eq) + 1e-5f);
    float* orow = out + (size_t)row * Eq;
    #pragma unroll
    for (int u=0;u<16;u++){
        int c = lane + u*32;
        float o = (v[u]-mean)*rstd*g[c] + b[c];
        orow[c] = o;
        if (WH) oh[(size_t)row*Eq + c] = __float2half_rn(o);
    }
}

// ============================================================================
// Launch
// ============================================================================
extern "C" void kernel_launch(void* const* d_in, const int* in_sizes, int n_in,
                              void* d_out, int out_size)
{
    const float* input = (const float*)d_in[0];
    const float* Wqkv  = (const float*)d_in[1];
    const float* bqkv  = (const float*)d_in[2];
    const float* W1    = (const float*)d_in[3];
    const float* b1    = (const float*)d_in[4];
    const float* W2    = (const float*)d_in[5];
    const float* b2    = (const float*)d_in[6];
    const float* g1    = (const float*)d_in[7];
    const float* bt1   = (const float*)d_in[8];
    const float* g2    = (const float*)d_in[9];
    const float* bt2   = (const float*)d_in[10];
    const float* g3    = (const float*)d_in[11];
    const float* bt3   = (const float*)d_in[12];

    float *x, *sv, *tb;
    bf16 *P;
    fp16 *xh,*qk,*aw,*xt,*hb,*Wq,*W1f,*W2f;
    cudaGetSymbolAddress((void**)&x,  g_x);
    cudaGetSymbolAddress((void**)&sv, g_sv);
    cudaGetSymbolAddress((void**)&tb, g_t);
    cudaGetSymbolAddress((void**)&P,  g_P);
    cudaGetSymbolAddress((void**)&xh, g_xh);
    cudaGetSymbolAddress((void**)&qk, g_qk);
    cudaGetSymbolAddress((void**)&aw, g_aw);
    cudaGetSymbolAddress((void**)&xt, g_xt);
    cudaGetSymbolAddress((void**)&hb, g_h);
    cudaGetSymbolAddress((void**)&Wq, g_Wq);
    cudaGetSymbolAddress((void**)&W1f,g_W1);
    cudaGetSymbolAddress((void**)&W2f,g_W2);

    cudaFuncSetAttribute(attn_exp, cudaFuncAttributeMaxDynamicSharedMemorySize, ATTN_SMEM);
    cudaFuncSetAttribute(mma_gemm2<0,0,1>, cudaFuncAttributeMaxDynamicSharedMemorySize, GEMM_SMEM);
    cudaFuncSetAttribute(mma_gemm2<0,1,0>, cudaFuncAttributeMaxDynamicSharedMemorySize, GEMM_SMEM);
    cudaFuncSetAttribute(mma_gemm2<1,0,1>, cudaFuncAttributeMaxDynamicSharedMemorySize, GEMM_SMEM);

    // one-time weight quantization + input copy/quant
    for (int d = 0; d < 4; d++){
        int n4 = 1024*512/4;
        quant_arr<<<(n4+255)/256, 256>>>(Wqkv + (size_t)d*1536*512,
                                         Wq + (size_t)d*1024*512, n4);
    }
    {
        int n4 = 4*2048*512/4;
        quant_arr<<<(n4+255)/256, 256>>>(W1, W1f, n4);
        quant_arr<<<(n4+255)/256, 256>>>(W2, W2f, n4);
    }
    {
        int n4 = Mq*Eq/4;
        quant_copy<<<(n4+255)/256, 256>>>(input, x, xh, n4);
    }

    for (int d = 0; d < 4; d++){
        const float* bq = bqkv + (size_t)d * 1536;

        // q|k projection -> fp16 qk (v/out-proj of Wqkv are dead in the reference)
        mma_gemm2<0,0,1><<<dim3(1024/256, Mq/128, 1), 256, GEMM_SMEM>>>(
            xh, Wq + (size_t)d*1024*512,
            bq, nullptr, qk, Mq, 1024, 512, 0, 0, 0, 0);

        // fused logits+exp (stores causal bf16 P, computes sinv)
        attn_exp<<<dim3(Bq*Hq, Lq/128), 256, ATTN_SMEM>>>(qk, P, sv);

        // fused head-average + second softmax -> fp16 attention weights
        make_w2<<<Bq*Lq, 256>>>(P, sv, aw);

        // sa = W @ x: fp16 transpose of x, then NT GEMM w/ causal k cutoff
        transpose_x<<<dim3(Eq/32, Lq/32, Bq), dim3(32,8)>>>(x, xt);
        mma_gemm2<0,1,0><<<dim3(Eq/256, Lq/128, Bq), 256, GEMM_SMEM>>>(
            aw, xt, nullptr, tb, nullptr,
            Lq, Eq, Lq, (long)Lq*Lq, (long)Eq*Lq, (long)Lq*Eq, 1);

        // x = LN2(LN1(x + sa))  (cross-attn block is a double-LN no-op)
        add_ln2<1><<<Mq/8, 256>>>(x, tb,
                                  g1 + d*Eq, bt1 + d*Eq,
                                  g2 + d*Eq, bt2 + d*Eq, x, xh);

        // FFN1 -> fp16 h (relu), FFN2 -> fp32 tb
        mma_gemm2<1,0,1><<<dim3(FFq/256, Mq/128, 1), 256, GEMM_SMEM>>>(
            xh, W1f + (size_t)d*2048*512,
            b1 + (size_t)d*FFq, nullptr, hb, Mq, FFq, Eq, 0, 0, 0, 0);
        mma_gemm2<0,1,0><<<dim3(Eq/256, Mq/128, 1), 256, GEMM_SMEM>>>(
            hb, W2f + (size_t)d*512*2048,
            b2 + (size_t)d*Eq, tb, nullptr, Mq, Eq, FFq, 0, 0, 0, 0);

        if (d == 3)
            add_ln1<0><<<Mq/8, 256>>>(x, tb, g3 + d*Eq, bt3 + d*Eq,
                                      (float*)d_out, nullptr);
        else
            add_ln1<1><<<Mq/8, 256>>>(x, tb, g3 + d*Eq, bt3 + d*Eq, x, xh);
    }
}

// round 11
// speedup vs baseline: 2.4158x; 1.0467x over previous
#include <cuda_runtime.h>
#include <cuda_fp16.h>
#include <cuda_bf16.h>
#include <math.h>
#include <stdint.h>

// Problem constants
#define Bq   8
#define Lq   1024
#define Eq   512
#define Hq   8
#define FFq  2048
#define Mq   (Bq*Lq)          // 8192 tokens

typedef __half        fp16;
typedef __nv_bfloat16 bf16;

// ---------------- scratch (static device globals; allocation-free) ----------
__device__ float g_x [Mq*Eq];        // current activations (fp32, residual path)
__device__ float g_sv[Bq*Hq*Lq];     // per-(b,h,i) 0.125/sum(exp)
__device__ float g_t [Mq*Eq];        // sa / ff temp (fp32)
__device__ bf16  g_P [(size_t)Bq*Hq*Lq*Lq];  // per-head exp(logits), bf16, causal tiles

// fp16 buffers (plain quantized)
__device__ fp16 g_xh [Mq*Eq];
__device__ fp16 g_qk [Mq*1024];
__device__ fp16 g_aw [(size_t)Bq*Lq*Lq];
__device__ fp16 g_xt [Bq*Eq*Lq];
__device__ fp16 g_h  [Mq*FFq];
__device__ fp16 g_Wq [4*1024*512];
__device__ fp16 g_W1 [4*2048*512];
__device__ fp16 g_W2 [4*512*2048];

// ---------------- helpers ------------------------------------------------------
__device__ __forceinline__ float warp_sum(float s){
    #pragma unroll
    for (int o=16;o;o>>=1) s += __shfl_xor_sync(0xffffffffu, s, o);
    return s;
}
__device__ __forceinline__ uint32_t hquant(float x0, float x1){
    return (uint32_t)__half_as_ushort(__float2half_rn(x0)) |
           ((uint32_t)__half_as_ushort(__float2half_rn(x1)) << 16);
}
__device__ __forceinline__ uint32_t bpack(float x0, float x1){
    __nv_bfloat162 b = __floats2bfloat162_rn(x0, x1);
    return *(uint32_t*)&b;
}
__device__ __forceinline__ uint32_t smem_u32(const void* p){
    uint32_t a;
    asm("{ .reg .u64 t; cvta.to.shared.u64 t, %1; cvt.u32.u64 %0, t; }" : "=r"(a) : "l"(p));
    return a;
}
__device__ __forceinline__ void cp16(uint32_t dst, const void* src){
    asm volatile("cp.async.cg.shared.global [%0], [%1], 16;" :: "r"(dst), "l"(src));
}
#define CP_COMMIT() asm volatile("cp.async.commit_group;" ::: "memory")
#define CP_WAIT0()  asm volatile("cp.async.wait_group 0;" ::: "memory")
#define CP_WAIT1()  asm volatile("cp.async.wait_group 1;" ::: "memory")

#define LDSM_X4(r, addr) \
    asm volatile("ldmatrix.sync.aligned.m8n8.x4.shared.b16 {%0,%1,%2,%3}, [%4];" \
        : "=r"((r)[0]), "=r"((r)[1]), "=r"((r)[2]), "=r"((r)[3]) : "r"(addr))

__device__ __forceinline__ void mma16816(float* c, const uint32_t* a, const uint32_t* b){
    asm volatile(
        "mma.sync.aligned.m16n8k16.row.col.f32.f16.f16.f32 "
        "{%0,%1,%2,%3}, {%4,%5,%6,%7}, {%8,%9}, {%0,%1,%2,%3};\n"
        : "+f"(c[0]), "+f"(c[1]), "+f"(c[2]), "+f"(c[3])
        : "r"(a[0]), "r"(a[1]), "r"(a[2]), "r"(a[3]), "r"(b[0]), "r"(b[1]));
}

// ============================================================================
// Quantization kernels: fp32 -> fp16 (optionally keep fp32 copy)
// ============================================================================
__global__ __launch_bounds__(256) void quant_arr(
    const float* __restrict__ in, fp16* __restrict__ oh, int n4)
{
    int i = blockIdx.x*256 + threadIdx.x;
    if (i >= n4) return;
    float4 v = ((const float4*)in)[i];
    ((uint2*)oh)[i] = make_uint2(hquant(v.x, v.y), hquant(v.z, v.w));
}

__global__ __launch_bounds__(256) void quant_copy(
    const float* __restrict__ in, float* __restrict__ out,
    fp16* __restrict__ oh, int n4)
{
    int i = blockIdx.x*256 + threadIdx.x;
    if (i >= n4) return;
    float4 v = ((const float4*)in)[i];
    ((float4*)out)[i] = v;
    ((uint2*)oh)[i] = make_uint2(hquant(v.x, v.y), hquant(v.z, v.w));
}

// ============================================================================
// Tensor-core GEMM NT, fp16 x fp16, fp32 accumulate.
// Tile 128(M) x 256(N), BK=32, 256 threads (2x4 warps, 64x64 each),
// 3-stage cp.async ring, single __syncthreads per chunk, ldmatrix fragments.
//   C[M,N] = A[M,K] * B[N,K]^T (+bias, relu), batched via z.
// ============================================================================
#define SA_U32   2560                   // A stage: 128 rows * 20 u32
#define SB_U32   5120                   // B stage: 256 rows * 20 u32
#define STG_U32  (SA_U32 + SB_U32)      // 7680
#define GEMM_SMEM (3 * STG_U32 * 4)     // 92160 B

template<int RELU, int WF32, int WH16>
__global__ __launch_bounds__(256, 1) void mma_gemm2(
    const fp16* __restrict__ Ah, const fp16* __restrict__ Bh,
    const float* __restrict__ bias,
    float* __restrict__ C, fp16* __restrict__ Ch,
    int M, int N, int K, long sA, long sB, long sC, int causal)
{
    extern __shared__ uint32_t sg[];
    const int bm = blockIdx.y * 128, bn = blockIdx.x * 256;
    const fp16* Abh = Ah + (size_t)blockIdx.z * sA;
    const fp16* Bbh = Bh + (size_t)blockIdx.z * sB;

    const int t    = threadIdx.x;
    const int lane = t & 31, wid = t >> 5;
    const int wm   = wid >> 2, wn = wid & 3;
    const int gid  = lane >> 2, tig = lane & 3;
    const int fr   = t >> 1, half = t & 1;

    float acc[4][8][4];
    #pragma unroll
    for (int i=0;i<4;i++)
        #pragma unroll
        for (int j=0;j<8;j++)
            #pragma unroll
            for (int q=0;q<4;q++) acc[i][j][q] = 0.f;

    const uint32_t sbase = smem_u32(sg);
    // cp.async fill addresses
    const uint32_t da  = sbase + (fr*20 + half*8)*4;
    const uint32_t db0 = sbase + (SA_U32 + fr*20 + half*8)*4;
    const uint32_t db1 = db0 + 128*20*4;
    const fp16* ga  = Abh + (size_t)(bm+fr)*K + half*16;
    const fp16* gb0 = Bbh + (size_t)(bn+fr)*K + half*16;
    const fp16* gb1 = Bbh + (size_t)(bn+128+fr)*K + half*16;

    // ldmatrix base addresses (per lane)
    // A: x4 per (mi,ks): rows R..R+15, 16B col (lane>>4)
    const uint32_t aB = sbase + (uint32_t)((wm*64 + (lane & 15))*20)*4 + (uint32_t)(lane >> 4)*16;
    // B: x4 per (np,ks): rows N0 + ((lane>>4)<<3) + (lane&7), 16B col ((lane>>3)&1)
    const uint32_t bB = sbase + (uint32_t)(SA_U32)*4 +
        (uint32_t)((wn*64 + ((lane >> 4) << 3) + (lane & 7))*20)*4 +
        (uint32_t)((lane >> 3) & 1)*16;

    const int kend = causal ? (bm + 128) : K;
    const int nch  = kend >> 5;

    #define G_ISSUE(ch_) do{ \
        const uint32_t st_ = (uint32_t)((ch_) % 3) * (STG_U32*4); \
        const fp16* A0_ = ga  + ((ch_) << 5); \
        const fp16* B0_ = gb0 + ((ch_) << 5); \
        const fp16* B1_ = gb1 + ((ch_) << 5); \
        cp16(da  + st_, A0_);  cp16(da  + st_ + 16, A0_ + 8); \
        cp16(db0 + st_, B0_);  cp16(db0 + st_ + 16, B0_ + 8); \
        cp16(db1 + st_, B1_);  cp16(db1 + st_ + 16, B1_ + 8); \
        CP_COMMIT(); }while(0)

    if (nch > 0) G_ISSUE(0);
    if (nch > 1) G_ISSUE(1);

    for (int ch = 0; ch < nch; ch++){
        if (ch + 1 < nch) CP_WAIT1(); else CP_WAIT0();
        __syncthreads();                 // stage ch visible; prior compute done
        if (ch + 2 < nch) G_ISSUE(ch+2); // safe: overwrites stage read 2 iters ago

        const uint32_t so = (uint32_t)(ch % 3) * (STG_U32*4);
        #pragma unroll
        for (int ks=0; ks<2; ks++){
            uint32_t ah[4][4], bf[4][4];
            #pragma unroll
            for (int mi=0;mi<4;mi++)
                LDSM_X4(ah[mi], aB + so + (uint32_t)mi*(16*80) + (uint32_t)ks*32);
            #pragma unroll
            for (int np=0;np<4;np++)
                LDSM_X4(bf[np], bB + so + (uint32_t)np*(16*80) + (uint32_t)ks*32);
            #pragma unroll
            for (int mi=0;mi<4;mi++){
                #pragma unroll
                for (int ni=0;ni<8;ni++){
                    uint32_t bb[2] = { bf[ni>>1][(ni&1)*2], bf[ni>>1][(ni&1)*2+1] };
                    mma16816(acc[mi][ni], ah[mi], bb);
                }
            }
        }
    }
    #undef G_ISSUE

    float* Cb  = WF32 ? C  + (size_t)blockIdx.z * sC : nullptr;
    fp16*  Chb = WH16 ? Ch + (size_t)blockIdx.z * sC : nullptr;
    #pragma unroll
    for (int mi=0;mi<4;mi++){
        int row = bm + wm*64 + mi*16 + gid;
        #pragma unroll
        for (int ni=0;ni<8;ni++){
            int col = bn + wn*64 + ni*8 + tig*2;
            float2 v0 = make_float2(acc[mi][ni][0], acc[mi][ni][1]);
            float2 v1 = make_float2(acc[mi][ni][2], acc[mi][ni][3]);
            if (bias){
                float2 bb = *(const float2*)(bias + col);
                v0.x += bb.x; v0.y += bb.y; v1.x += bb.x; v1.y += bb.y;
            }
            if (RELU){
                v0.x=fmaxf(v0.x,0.f); v0.y=fmaxf(v0.y,0.f);
                v1.x=fmaxf(v1.x,0.f); v1.y=fmaxf(v1.y,0.f);
            }
            if (WF32){
                *(float2*)(Cb + (size_t)row    *N + col) = v0;
                *(float2*)(Cb + (size_t)(row+8)*N + col) = v1;
            }
            if (WH16){
                *(uint32_t*)(Chb + (size_t)row    *N + col) = hquant(v0.x, v0.y);
                *(uint32_t*)(Chb + (size_t)(row+8)*N + col) = hquant(v1.x, v1.y);
            }
        }
    }
}

// ============================================================================
// Fused attention exp kernel, fp16, 3-stage cp.async K ring, ldmatrix frags:
// per (b,h,i0): logits = Q*K^T/8; E = exp; row sums -> sinv;
// store E (bf16) to P for causal tiles.
// Dyn smem: sQ (4608 u32) + 3 K stages (4608 u32 each) = 73728 B
// ============================================================================
#define ATTN_SMEM (4*4608*4)
__global__ __launch_bounds__(256) void attn_exp(
    const fp16* __restrict__ qk,
    bf16* __restrict__ P, float* __restrict__ sinv)
{
    extern __shared__ uint32_t smx[];
    uint32_t* sQh = smx;
    uint32_t* sK  = smx + 4608;
    __shared__ float sred[128];

    const int bh = blockIdx.x;
    const int ti = blockIdx.y;
    const int i0 = ti * 128;
    const int b  = bh >> 3, h = bh & 7;
    const size_t qoff = (size_t)(b*Lq)*1024 + h*64;

    const int t = threadIdx.x;
    const int lane = t & 31, wid = t >> 5;
    const int wm = wid >> 2, wn = wid & 3;
    const int gid = lane >> 2, tig = lane & 3;
    const int fr = t >> 1, half = t & 1;

    if (t < 128) sred[t] = 0.f;

    const uint32_t dk = smem_u32(sK) + fr*144 + half*64;
    const fp16* gk = qk + qoff + 512 + (size_t)fr*1024 + half*32;

    #define K_ISSUE(jt_) do{ \
        const uint32_t st_ = (uint32_t)((jt_) % 3) * 18432; \
        const fp16* g_ = gk + (size_t)(jt_)*128*1024; \
        cp16(dk + st_,      g_);       cp16(dk + st_ + 16, g_ + 8); \
        cp16(dk + st_ + 32, g_ + 16);  cp16(dk + st_ + 48, g_ + 24); \
        CP_COMMIT(); }while(0)

    K_ISSUE(0);
    K_ISSUE(1);

    // load Q tile [128 x 64]
    {
        const uint4* sh = (const uint4*)(qk + qoff + (size_t)(i0+fr)*1024 + half*32);
        uint4* dh = (uint4*)(sQh + fr*36 + half*16);
        dh[0]=sh[0]; dh[1]=sh[1]; dh[2]=sh[2]; dh[3]=sh[3];
    }

    // ldmatrix base addresses (stride 36 u32 = 144 B)
    const uint32_t qB = smem_u32(sQh) +
        (uint32_t)((wm*64 + (lane & 15))*36)*4 + (uint32_t)(lane >> 4)*16;
    const uint32_t kB = smem_u32(sK) +
        (uint32_t)((wn*32 + ((lane >> 4) << 3) + (lane & 7))*36)*4 +
        (uint32_t)((lane >> 3) & 1)*16;

    float rsum[4][2];
    #pragma unroll
    for (int mi=0;mi<4;mi++){ rsum[mi][0]=0.f; rsum[mi][1]=0.f; }

    for (int jt = 0; jt < Lq/128; jt++){
        if (jt + 1 < Lq/128) CP_WAIT1(); else CP_WAIT0();
        __syncthreads();
        if (jt + 2 < Lq/128) K_ISSUE(jt+2);

        const uint32_t so = (uint32_t)(jt % 3) * 18432;
        float acc[4][4][4];
        #pragma unroll
        for (int i=0;i<4;i++)
            #pragma unroll
            for (int j=0;j<4;j++)
                #pragma unroll
                for (int q=0;q<4;q++) acc[i][j][q] = 0.f;

        #pragma unroll
        for (int ks=0; ks<4; ks++){
            uint32_t ah[4][4], bf[2][4];
            #pragma unroll
            for (int mi=0;mi<4;mi++)
                LDSM_X4(ah[mi], qB + (uint32_t)mi*(16*144) + (uint32_t)ks*32);
            #pragma unroll
            for (int np=0;np<2;np++)
                LDSM_X4(bf[np], kB + so + (uint32_t)np*(16*144) + (uint32_t)ks*32);
            #pragma unroll
            for (int mi=0;mi<4;mi++){
                #pragma unroll
                for (int ni=0;ni<4;ni++){
                    uint32_t bb[2] = { bf[ni>>1][(ni&1)*2], bf[ni>>1][(ni&1)*2+1] };
                    mma16816(acc[mi][ni], ah[mi], bb);
                }
            }
        }

        const int j0 = jt * 128;
        const bool store = (jt <= ti);
        #pragma unroll
        for (int mi=0;mi<4;mi++){
            const int row = i0 + wm*64 + mi*16 + gid;
            #pragma unroll
            for (int ni=0;ni<4;ni++){
                float e0 = __expf(acc[mi][ni][0] * 0.125f);
                float e1 = __expf(acc[mi][ni][1] * 0.125f);
                float e2 = __expf(acc[mi][ni][2] * 0.125f);
                float e3 = __expf(acc[mi][ni][3] * 0.125f);
                rsum[mi][0] += e0 + e1;
                rsum[mi][1] += e2 + e3;
                if (store){
                    const int col = j0 + wn*32 + ni*8 + tig*2;
                    bf16* p0 = P + ((size_t)bh*Lq + row)*Lq + col;
                    *(uint32_t*)p0          = bpack(e0, e1);
                    *(uint32_t*)(p0 + 8*Lq) = bpack(e2, e3);
                }
            }
        }
    }
    #undef K_ISSUE

    #pragma unroll
    for (int mi=0;mi<4;mi++){
        float r0 = rsum[mi][0], r1 = rsum[mi][1];
        r0 += __shfl_xor_sync(0xffffffffu, r0, 1);
        r0 += __shfl_xor_sync(0xffffffffu, r0, 2);
        r1 += __shfl_xor_sync(0xffffffffu, r1, 1);
        r1 += __shfl_xor_sync(0xffffffffu, r1, 2);
        if (tig == 0){
            atomicAdd(&sred[wm*64 + mi*16 + gid    ], r0);
            atomicAdd(&sred[wm*64 + mi*16 + gid + 8], r1);
        }
    }
    __syncthreads();
    if (t < 128)
        sinv[(size_t)bh*Lq + i0 + t] = 0.125f / sred[t];
}

// ============================================================================
// Fused head-average + second softmax (A never materialized):
// per (b,i): a[j] = sum_h P[b,h,i,j]*sinv[b,h,i];
// W = softmax_{j<=i}( a + exp((j-i)*0.1) ); writes fp16 W.
// ============================================================================
__global__ __launch_bounds__(256) void make_w2(
    const bf16* __restrict__ P, const float* __restrict__ sinv,
    fp16* __restrict__ Wh)
{
    const int row = blockIdx.x;            // b*1024 + i
    const int b = row >> 10, i = row & 1023;
    const int t = threadIdx.x;
    __shared__ float sv8[8];
    if (t < 8) sv8[t] = sinv[(size_t)(b*8 + t)*Lq + i];
    __syncthreads();

    const int j0 = t*4;
    float v[4] = {0.f,0.f,0.f,0.f};
    float s = 0.f;
    if (j0 <= i){
        float a[4] = {0.f,0.f,0.f,0.f};
        const bf16* pb = P + ((size_t)(b*8)*Lq + i)*Lq + j0;
        #pragma unroll
        for (int h=0; h<8; h++){
            const uint2 pv = *(const uint2*)(pb + (size_t)h*Lq*Lq);
            const float sc = sv8[h];
            float2 f0 = __bfloat1622float2(*(const __nv_bfloat162*)&pv.x);
            float2 f1 = __bfloat1622float2(*(const __nv_bfloat162*)&pv.y);
            a[0] = fmaf(f0.x, sc, a[0]); a[1] = fmaf(f0.y, sc, a[1]);
            a[2] = fmaf(f1.x, sc, a[2]); a[3] = fmaf(f1.y, sc, a[3]);
        }
        #pragma unroll
        for (int u=0;u<4;u++){
            int j = j0 + u;
            if (j <= i){
                float pos = __expf((float)(j - i) * 0.1f);
                v[u] = __expf(a[u] + pos);
                s += v[u];
            }
        }
    }
    s = warp_sum(s);
    __shared__ float red[8];
    if ((t & 31) == 0) red[t >> 5] = s;
    __syncthreads();
    float tot = 0.f;
    #pragma unroll
    for (int w=0;w<8;w++) tot += red[w];
    float inv = 1.f / tot;
    *(uint2*)(Wh + (size_t)row*Lq + j0) =
        make_uint2(hquant(v[0]*inv, v[1]*inv), hquant(v[2]*inv, v[3]*inv));
}

// ============================================================================
// Batched transpose + quantize: xt[b][e][l] = fp16(x[b][l][e])
// ============================================================================
__global__ __launch_bounds__(256) void transpose_x(
    const float* __restrict__ x, fp16* __restrict__ xt)
{
    __shared__ float tile[32][33];
    const int b  = blockIdx.z;
    const int l0 = blockIdx.y * 32, e0 = blockIdx.x * 32;
    const float* xp = x + (size_t)b * Lq * Eq;
    const int tx = threadIdx.x, ty = threadIdx.y;
    #pragma unroll
    for (int j=0;j<32;j+=8)
        tile[ty+j][tx] = xp[(size_t)(l0+ty+j)*Eq + e0 + tx];
    __syncthreads();
    const size_t base = (size_t)b * Eq * Lq;
    #pragma unroll
    for (int j=0;j<32;j+=8)
        xt[base + (size_t)(e0+ty+j)*Lq + l0 + tx] = __float2half_rn(tile[tx][ty+j]);
}

// ============================================================================
// LayerNorm kernels (one warp per 512-wide row); optional fp16 output
// ============================================================================
template<int WH>
__global__ __launch_bounds__(256) void add_ln2(
    const float* __restrict__ x, const float* __restrict__ y,
    const float* __restrict__ g1, const float* __restrict__ b1,
    const float* __restrict__ g2, const float* __restrict__ b2,
    float* __restrict__ out, fp16* __restrict__ oh)
{
    const int row  = blockIdx.x * 8 + (threadIdx.x >> 5);
    const int lane = threadIdx.x & 31;
    const float* xr = x + (size_t)row * Eq;
    const float* yr = y + (size_t)row * Eq;
    float v[16]; float s = 0.f;
    #pragma unroll
    for (int u=0;u<16;u++){ int c = lane + u*32; v[u] = xr[c] + yr[c]; s += v[u]; }
    s = warp_sum(s);
    float mean = s * (1.0f/Eq);
    float sq = 0.f;
    #pragma unroll
    for (int u=0;u<16;u++){ float d = v[u]-mean; sq += d*d; }
    sq = warp_sum(sq);
    float rstd = rsqrtf(sq*(1.0f/Eq) + 1e-5f);
    float s2 = 0.f;
    #pragma unroll
    for (int u=0;u<16;u++){ int c = lane + u*32; v[u] = (v[u]-mean)*rstd*g1[c] + b1[c]; s2 += v[u]; }
    s2 = warp_sum(s2);
    float m2 = s2 * (1.0f/Eq);
    float q2 = 0.f;
    #pragma unroll
    for (int u=0;u<16;u++){ float d = v[u]-m2; q2 += d*d; }
    q2 = warp_sum(q2);
    float r2 = rsqrtf(q2*(1.0f/Eq) + 1e-5f);
    float* orow = out + (size_t)row * Eq;
    #pragma unroll
    for (int u=0;u<16;u++){
        int c = lane + u*32;
        float o = (v[u]-m2)*r2*g2[c] + b2[c];
        orow[c] = o;
        if (WH) oh[(size_t)row*Eq + c] = __float2half_rn(o);
    }
}

template<int WH>
__global__ __launch_bounds__(256) void add_ln1(
    const float* __restrict__ x, const float* __restrict__ y,
    const float* __restrict__ g, const float* __restrict__ b,
    float* __restrict__ out, fp16* __restrict__ oh)
{
    const int row  = blockIdx.x * 8 + (threadIdx.x >> 5);
    const int lane = threadIdx.x & 31;
    const float* xr = x + (size_t)row * Eq;
    const float* yr = y + (size_t)row * Eq;
    float v[16]; float s = 0.f;
    #pragma unroll
    for (int u=0;u<16;u++){ int c = lane + u*32; v[u] = xr[c] + yr[c]; s += v[u]; }
    s = warp_sum(s);
    float mean = s * (1.0f/Eq);
    float sq = 0.f;
    #pragma unroll
    for (int u=0;u<16;u++){ float d = v[u]-mean; sq += d*d; }
    sq = warp_sum(sq);
    float rstd = rsqrtf(sq*(1.0f/Eq) + 1e-5f);
    float* orow = out + (size_t)row * Eq;
    #pragma unroll
    for (int u=0;u<16;u++){
        int c = lane + u*32;
        float o = (v[u]-mean)*rstd*g[c] + b[c];
        orow[c] = o;
        if (WH) oh[(size_t)row*Eq + c] = __float2half_rn(o);
    }
}

// ============================================================================
// Launch
// ============================================================================
extern "C" void kernel_launch(void* const* d_in, const int* in_sizes, int n_in,
                              void* d_out, int out_size)
{
    const float* input = (const float*)d_in[0];
    const float* Wqkv  = (const float*)d_in[1];
    const float* bqkv  = (const float*)d_in[2];
    const float* W1    = (const float*)d_in[3];
    const float* b1    = (const float*)d_in[4];
    const float* W2    = (const float*)d_in[5];
    const float* b2    = (const float*)d_in[6];
    const float* g1    = (const float*)d_in[7];
    const float* bt1   = (const float*)d_in[8];
    const float* g2    = (const float*)d_in[9];
    const float* bt2   = (const float*)d_in[10];
    const float* g3    = (const float*)d_in[11];
    const float* bt3   = (const float*)d_in[12];

    float *x, *sv, *tb;
    bf16 *P;
    fp16 *xh,*qk,*aw,*xt,*hb,*Wq,*W1f,*W2f;
    cudaGetSymbolAddress((void**)&x,  g_x);
    cudaGetSymbolAddress((void**)&sv, g_sv);
    cudaGetSymbolAddress((void**)&tb, g_t);
    cudaGetSymbolAddress((void**)&P,  g_P);
    cudaGetSymbolAddress((void**)&xh, g_xh);
    cudaGetSymbolAddress((void**)&qk, g_qk);
    cudaGetSymbolAddress((void**)&aw, g_aw);
    cudaGetSymbolAddress((void**)&xt, g_xt);
    cudaGetSymbolAddress((void**)&hb, g_h);
    cudaGetSymbolAddress((void**)&Wq, g_Wq);
    cudaGetSymbolAddress((void**)&W1f,g_W1);
    cudaGetSymbolAddress((void**)&W2f,g_W2);

    cudaFuncSetAttribute(attn_exp, cudaFuncAttributeMaxDynamicSharedMemorySize, ATTN_SMEM);
    cudaFuncSetAttribute(mma_gemm2<0,0,1>, cudaFuncAttributeMaxDynamicSharedMemorySize, GEMM_SMEM);
    cudaFuncSetAttribute(mma_gemm2<0,1,0>, cudaFuncAttributeMaxDynamicSharedMemorySize, GEMM_SMEM);
    cudaFuncSetAttribute(mma_gemm2<1,0,1>, cudaFuncAttributeMaxDynamicSharedMemorySize, GEMM_SMEM);

    // one-time weight quantization + input copy/quant
    for (int d = 0; d < 4; d++){
        int n4 = 1024*512/4;
        quant_arr<<<(n4+255)/256, 256>>>(Wqkv + (size_t)d*1536*512,
                                         Wq + (size_t)d*1024*512, n4);
    }
    {
        int n4 = 4*2048*512/4;
        quant_arr<<<(n4+255)/256, 256>>>(W1, W1f, n4);
        quant_arr<<<(n4+255)/256, 256>>>(W2, W2f, n4);
    }
    {
        int n4 = Mq*Eq/4;
        quant_copy<<<(n4+255)/256, 256>>>(input, x, xh, n4);
    }

    for (int d = 0; d < 4; d++){
        const float* bq = bqkv + (size_t)d * 1536;

        // q|k projection -> fp16 qk (v/out-proj of Wqkv are dead in the reference)
        mma_gemm2<0,0,1><<<dim3(1024/256, Mq/128, 1), 256, GEMM_SMEM>>>(
            xh, Wq + (size_t)d*1024*512,
            bq, nullptr, qk, Mq, 1024, 512, 0, 0, 0, 0);

        // fused logits+exp (stores causal bf16 P, computes sinv)
        attn_exp<<<dim3(Bq*Hq, Lq/128), 256, ATTN_SMEM>>>(qk, P, sv);

        // fused head-average + second softmax -> fp16 attention weights
        make_w2<<<Bq*Lq, 256>>>(P, sv, aw);

        // sa = W @ x: fp16 transpose of x, then NT GEMM w/ causal k cutoff
        transpose_x<<<dim3(Eq/32, Lq/32, Bq), dim3(32,8)>>>(x, xt);
        mma_gemm2<0,1,0><<<dim3(Eq/256, Lq/128, Bq), 256, GEMM_SMEM>>>(
            aw, xt, nullptr, tb, nullptr,
            Lq, Eq, Lq, (long)Lq*Lq, (long)Eq*Lq, (long)Lq*Eq, 1);

        // x = LN2(LN1(x + sa))  (cross-attn block is a double-LN no-op)
        add_ln2<1><<<Mq/8, 256>>>(x, tb,
                                  g1 + d*Eq, bt1 + d*Eq,
                                  g2 + d*Eq, bt2 + d*Eq, x, xh);

        // FFN1 -> fp16 h (relu), FFN2 -> fp32 tb
        mma_gemm2<1,0,1><<<dim3(FFq/256, Mq/128, 1), 256, GEMM_SMEM>>>(
            xh, W1f + (size_t)d*2048*512,
            b1 + (size_t)d*FFq, nullptr, hb, Mq, FFq, Eq, 0, 0, 0, 0);
        mma_gemm2<0,1,0><<<dim3(Eq/256, Mq/128, 1), 256, GEMM_SMEM>>>(
            hb, W2f + (size_t)d*512*2048,
            b2 + (size_t)d*Eq, tb, nullptr, Mq, Eq, FFq, 0, 0, 0, 0);

        if (d == 3)
            add_ln1<0><<<Mq/8, 256>>>(x, tb, g3 + d*Eq, bt3 + d*Eq,
                                      (float*)d_out, nullptr);
        else
            add_ln1<1><<<Mq/8, 256>>>(x, tb, g3 + d*Eq, bt3 + d*Eq, x, xh);
    }
}